// round 5
// baseline (speedup 1.0000x reference)
#include <cuda_runtime.h>

// Problem constants
#define EMB   768
#define NH    12
#define HD    64
#define SEQ   8192
#define QKV3  2304          // 3*EMB
#define QSCALE 0.125f       // 1/sqrt(64)

// ---------------------------------------------------------------------------
// Scratch (device globals — no runtime allocation allowed)
// ---------------------------------------------------------------------------
__device__ float g_qkv[SEQ * QKV3];   // [S][3E] : q at +0, k at +768, v at +1536 (per head h: h*64+d)
__device__ float g_attn[SEQ * EMB];   // [S][E]  : mean of branch outputs, layout s*768 + h*64 + d

// ---------------------------------------------------------------------------
// Generic fp32 GEMM with bias:  C[M,N] = A[M,K] * B[K,N] + bias[N]
// Block tile 64x64, BK=16, 256 threads, 4x4 register micro-tile per thread.
// Requires M%64==0, N%64==0, K%16==0 (true for all uses here).
// ---------------------------------------------------------------------------
__global__ __launch_bounds__(256)
void gemm_bias_kernel(const float* __restrict__ A,
                      const float* __restrict__ B,
                      const float* __restrict__ bias,
                      float* __restrict__ C,
                      int M, int N, int K)
{
    __shared__ float Ast[16 * 68];   // [kk][m], padded
    __shared__ float Bs [16 * 68];   // [kk][n], padded

    const int tid = threadIdx.x;
    const int ty  = tid >> 4;        // 0..15
    const int tx  = tid & 15;        // 0..15
    const int m0  = blockIdx.y * 64;
    const int n0  = blockIdx.x * 64;

    float acc[4][4] = {};

    for (int k0 = 0; k0 < K; k0 += 16) {
        // Load A tile 64x16 -> transposed Ast[kk][m]
        {
            const int kk = tid & 15;          // 0..15
            const int mb = tid >> 4;          // 0..15
            #pragma unroll
            for (int i = 0; i < 4; i++) {
                const int m = mb + 16 * i;
                Ast[kk * 68 + m] = A[(size_t)(m0 + m) * K + k0 + kk];
            }
        }
        // Load B tile 16x64 -> Bs[kk][n]
        {
            const int n  = tid & 63;          // 0..63
            const int kb = tid >> 6;          // 0..3
            #pragma unroll
            for (int i = 0; i < 4; i++) {
                const int kk = kb + 4 * i;
                Bs[kk * 68 + n] = B[(size_t)(k0 + kk) * N + n0 + n];
            }
        }
        __syncthreads();

        #pragma unroll
        for (int kk = 0; kk < 16; kk++) {
            float ar[4], br[4];
            *(float4*)ar = *(const float4*)&Ast[kk * 68 + 4 * ty];
            *(float4*)br = *(const float4*)&Bs [kk * 68 + 4 * tx];
            #pragma unroll
            for (int i = 0; i < 4; i++)
                #pragma unroll
                for (int j = 0; j < 4; j++)
                    acc[i][j] += ar[i] * br[j];
        }
        __syncthreads();
    }

    // Epilogue: add bias, store
    #pragma unroll
    for (int i = 0; i < 4; i++) {
        const int m = m0 + 4 * ty + i;
        float4 v;
        v.x = acc[i][0] + bias[n0 + 4 * tx + 0];
        v.y = acc[i][1] + bias[n0 + 4 * tx + 1];
        v.z = acc[i][2] + bias[n0 + 4 * tx + 2];
        v.w = acc[i][3] + bias[n0 + 4 * tx + 3];
        *(float4*)&C[(size_t)m * N + n0 + 4 * tx] = v;
    }
}

// ---------------------------------------------------------------------------
// Strided flash attention, all 3 dilation branches in one launch.
//   branch 0: L=2048, stride=1
//   branch 1: L=4096, stride=2
//   branch 2: L=2048, stride=4
// Block = 64 queries of one head of one branch; 256 threads.
// Online softmax; epilogue atomicAdd( o/l * 1/3 ) into g_attn (pre-zeroed).
// ---------------------------------------------------------------------------
__global__ __launch_bounds__(256)
void attn_kernel(const float* __restrict__ qkv, float* __restrict__ attn_out)
{
    extern __shared__ float sm[];
    float* Qst  = sm;                 // [d:64][q:64] pitch 68  (Q * QSCALE, transposed)
    float* Kst  = Qst + 64 * 68;      // [d:64][k:64] pitch 68
    float* Vs   = Kst + 64 * 68;      // [k:64][d:64] pitch 64
    float* Ss   = Vs  + 64 * 64;      // [q:64][k:64] pitch 65
    float* Pt   = Ss  + 64 * 65;      // [k:64][q:64] pitch 64
    float* mrow = Pt  + 64 * 64;      // [64]
    float* lrow = mrow + 64;          // [64]
    float* arow = lrow + 64;          // [64]

    const int br = blockIdx.z;
    int L, stride;
    if (br == 0)      { L = 2048; stride = 1; }
    else if (br == 1) { L = 4096; stride = 2; }
    else              { L = 2048; stride = 4; }

    const int q0 = blockIdx.x * 64;
    if (q0 >= L) return;
    const int h   = blockIdx.y;
    const int tid = threadIdx.x;
    const int ty  = tid >> 4;   // 0..15
    const int tx  = tid & 15;   // 0..15

    // Load Q tile (scaled), transposed into Qst
    {
        const int d  = tid & 63;
        const int rb = tid >> 6;          // 0..3
        #pragma unroll
        for (int i = 0; i < 16; i++) {
            const int r   = rb * 16 + i;
            const int tok = (q0 + r) * stride;
            Qst[d * 68 + r] = qkv[(size_t)tok * QKV3 + h * 64 + d] * QSCALE;
        }
    }
    if (tid < 64) { mrow[tid] = -1e30f; lrow[tid] = 0.0f; }

    float o[4][4] = {};

    const int nkt = L >> 6;
    for (int kt = 0; kt < nkt; kt++) {
        __syncthreads();   // protect smem from previous iteration's readers

        // Load K (transposed) and V tiles
        {
            const int d  = tid & 63;
            const int kb = tid >> 6;      // 0..3
            #pragma unroll
            for (int i = 0; i < 16; i++) {
                const int k   = kb * 16 + i;
                const int tok = (kt * 64 + k) * stride;
                const float* base = qkv + (size_t)tok * QKV3 + h * 64 + d;
                Kst[d * 68 + k] = base[768];     // K
                Vs [k * 64 + d] = base[1536];    // V
            }
        }
        __syncthreads();

        // Phase 2: S = (Q*scale) K^T  (64x64), 4x4 per thread
        float s44[4][4] = {};
        #pragma unroll 16
        for (int d = 0; d < 64; d++) {
            float ar[4], br4[4];
            *(float4*)ar  = *(const float4*)&Qst[d * 68 + 4 * ty];
            *(float4*)br4 = *(const float4*)&Kst[d * 68 + 4 * tx];
            #pragma unroll
            for (int i = 0; i < 4; i++)
                #pragma unroll
                for (int j = 0; j < 4; j++)
                    s44[i][j] += ar[i] * br4[j];
        }
        #pragma unroll
        for (int i = 0; i < 4; i++)
            #pragma unroll
            for (int j = 0; j < 4; j++)
                Ss[(4 * ty + i) * 65 + 4 * tx + j] = s44[i][j];
        __syncthreads();

        // Phase 3: per-row online softmax update (64 threads, one row each)
        if (tid < 64) {
            const int r = tid;
            const float mold = mrow[r];
            float mnew = mold;
            #pragma unroll 8
            for (int k = 0; k < 64; k++)
                mnew = fmaxf(mnew, Ss[r * 65 + k]);
            const float alpha = __expf(mold - mnew);
            float lsum = lrow[r] * alpha;
            #pragma unroll 8
            for (int k = 0; k < 64; k++) {
                const float p = __expf(Ss[r * 65 + k] - mnew);
                Pt[k * 64 + r] = p;
                lsum += p;
            }
            mrow[r] = mnew;
            lrow[r] = lsum;
            arow[r] = alpha;
        }
        __syncthreads();

        // Phase 4: O = O*alpha + P~ * V   (register accumulators)
        float al[4];
        *(float4*)al = *(const float4*)&arow[4 * ty];
        #pragma unroll
        for (int i = 0; i < 4; i++)
            #pragma unroll
            for (int j = 0; j < 4; j++)
                o[i][j] *= al[i];
        #pragma unroll 16
        for (int k = 0; k < 64; k++) {
            float pr[4], vr[4];
            *(float4*)pr = *(const float4*)&Pt[k * 64 + 4 * ty];
            *(float4*)vr = *(const float4*)&Vs[k * 64 + 4 * tx];
            #pragma unroll
            for (int i = 0; i < 4; i++)
                #pragma unroll
                for (int j = 0; j < 4; j++)
                    o[i][j] += pr[i] * vr[j];
        }
    }

    // Epilogue: divide by l, weight by 1/3 (mean over 3 branches), scatter-add
    const float w = 1.0f / 3.0f;
    #pragma unroll
    for (int i = 0; i < 4; i++) {
        const int   r    = 4 * ty + i;
        const float linv = w / lrow[r];
        const int   tok  = (q0 + r) * stride;
        float* dst = attn_out + (size_t)tok * EMB + h * 64 + 4 * tx;
        #pragma unroll
        for (int j = 0; j < 4; j++)
            atomicAdd(&dst[j], o[i][j] * linv);
    }
}

// ---------------------------------------------------------------------------
// Launch
// ---------------------------------------------------------------------------
extern "C" void kernel_launch(void* const* d_in, const int* in_sizes, int n_in,
                              void* d_out, int out_size)
{
    const float* x    = (const float*)d_in[0];   // [1,8192,768]
    const float* Wqkv = (const float*)d_in[1];   // [768,2304]
    const float* bqkv = (const float*)d_in[2];   // [2304]
    const float* Wout = (const float*)d_in[3];   // [768,768]
    const float* bout = (const float*)d_in[4];   // [768]
    float*       out  = (float*)d_out;           // [1,8192,768]

    float *qkvp = nullptr, *attnp = nullptr;
    cudaGetSymbolAddress((void**)&qkvp, g_qkv);
    cudaGetSymbolAddress((void**)&attnp, g_attn);

    // Dynamic smem for attention: 21248 floats = 84992 bytes.
    // Idempotent; if ignored during capture, the first (uncaptured) correctness
    // call has already set it.
    (void)cudaFuncSetAttribute((const void*)attn_kernel,
                               cudaFuncAttributeMaxDynamicSharedMemorySize, 84992);

    // 1) QKV GEMM: [8192,768] x [768,2304] + bias
    {
        dim3 grid(QKV3 / 64, SEQ / 64);
        gemm_bias_kernel<<<grid, 256>>>(x, Wqkv, bqkv, qkvp, SEQ, QKV3, EMB);
    }

    // 2) Zero the attention accumulator
    cudaMemsetAsync(attnp, 0, (size_t)SEQ * EMB * sizeof(float));

    // 3) All 3 attention branches in one launch (grid.x sized for largest branch)
    {
        dim3 grid(64, NH, 3);
        attn_kernel<<<grid, 256, 84992>>>(qkvp, attnp);
    }

    // 4) Output projection: [8192,768] x [768,768] + bias -> d_out
    {
        dim3 grid(EMB / 64, SEQ / 64);
        gemm_bias_kernel<<<grid, 256>>>(attnp, Wout, bout, out, SEQ, EMB, EMB);
    }
}

// round 6
// speedup vs baseline: 1.4679x; 1.4679x over previous
#include <cuda_runtime.h>

// Problem constants
#define EMB   768
#define NH    12
#define HD    64
#define SEQ   8192
#define QKV3  2304          // 3*EMB
#define QSCALE 0.125f       // 1/sqrt(64)

typedef unsigned long long ull;

// ---------------------------------------------------------------------------
// Packed fp32x2 helpers (sm_100+): fma.rn.f32x2 doubles fp32 MAC density.
// ---------------------------------------------------------------------------
__device__ __forceinline__ ull dup2(float a) {
    ull d;
    asm("mov.b64 %0, {%1, %1};" : "=l"(d) : "r"(__float_as_uint(a)));
    return d;
}
__device__ __forceinline__ ull pack2(float lo, float hi) {
    ull d;
    asm("mov.b64 %0, {%1, %2};" : "=l"(d) : "r"(__float_as_uint(lo)), "r"(__float_as_uint(hi)));
    return d;
}
__device__ __forceinline__ void unpack2(ull d, float &lo, float &hi) {
    unsigned a, b;
    asm("mov.b64 {%0, %1}, %2;" : "=r"(a), "=r"(b) : "l"(d));
    lo = __uint_as_float(a); hi = __uint_as_float(b);
}
__device__ __forceinline__ void ffma2(ull &d, ull a, ull b) {
    asm("fma.rn.f32x2 %0, %1, %2, %0;" : "+l"(d) : "l"(a), "l"(b));
}
__device__ __forceinline__ void fmul2(ull &d, ull a) {
    asm("mul.rn.f32x2 %0, %0, %1;" : "+l"(d) : "l"(a));
}

// ---------------------------------------------------------------------------
// Scratch (device globals — no runtime allocation allowed)
// ---------------------------------------------------------------------------
__device__ float g_qkv[SEQ * QKV3];   // [S][3E] : q at +0, k at +768, v at +1536
__device__ float g_attn[SEQ * EMB];   // [S][E]  : mean of branch outputs

// ---------------------------------------------------------------------------
// fp32 GEMM + bias: C[M,N] = A[M,K]*B[K,N] + bias[N]
// 128x128 block tile, BK=16, 256 threads, 8x8 micro-tile, FFMA2 packed along N.
// Requires M%128==0, N%128==0, K%16==0.
// ---------------------------------------------------------------------------
__global__ __launch_bounds__(256, 2)
void gemm_bias_kernel(const float* __restrict__ A,
                      const float* __restrict__ B,
                      const float* __restrict__ bias,
                      float* __restrict__ C,
                      int M, int N, int K)
{
    __shared__ float Ast[16][132];   // [kk][m]
    __shared__ float Bs [16][132];   // [kk][n]

    const int tid = threadIdx.x;
    const int ty  = tid >> 4;        // 0..15 -> m block of 8
    const int tx  = tid & 15;        // 0..15 -> n block of 8
    const int m0  = blockIdx.y * 128;
    const int n0  = blockIdx.x * 128;

    ull acc[8][4];
    #pragma unroll
    for (int i = 0; i < 8; i++)
        #pragma unroll
        for (int j = 0; j < 4; j++) acc[i][j] = 0ull;

    const int a_k = (tid & 3) * 4;   // 0,4,8,12
    const int a_m = tid >> 2;        // 0..63
    const int b_n = (tid & 31) * 4;  // 0..124
    const int b_k = tid >> 5;        // 0..7

    for (int k0 = 0; k0 < K; k0 += 16) {
        // A tile 128x16 (float4 along K), store transposed
        #pragma unroll
        for (int i = 0; i < 2; i++) {
            const int m = a_m + 64 * i;
            float4 v = *(const float4*)&A[(size_t)(m0 + m) * K + k0 + a_k];
            Ast[a_k + 0][m] = v.x; Ast[a_k + 1][m] = v.y;
            Ast[a_k + 2][m] = v.z; Ast[a_k + 3][m] = v.w;
        }
        // B tile 16x128 (float4 along N)
        #pragma unroll
        for (int i = 0; i < 2; i++) {
            const int kk = b_k + 8 * i;
            *(float4*)&Bs[kk][b_n] = *(const float4*)&B[(size_t)(k0 + kk) * N + n0 + b_n];
        }
        __syncthreads();

        #pragma unroll
        for (int kk = 0; kk < 16; kk++) {
            float4 a0 = *(const float4*)&Ast[kk][8 * ty];
            float4 a1 = *(const float4*)&Ast[kk][8 * ty + 4];
            ulonglong2 bq0 = *(const ulonglong2*)&Bs[kk][8 * tx];
            ulonglong2 bq1 = *(const ulonglong2*)&Bs[kk][8 * tx + 4];
            ull ad[8] = { dup2(a0.x), dup2(a0.y), dup2(a0.z), dup2(a0.w),
                          dup2(a1.x), dup2(a1.y), dup2(a1.z), dup2(a1.w) };
            ull bp[4] = { bq0.x, bq0.y, bq1.x, bq1.y };
            #pragma unroll
            for (int i = 0; i < 8; i++)
                #pragma unroll
                for (int j = 0; j < 4; j++)
                    ffma2(acc[i][j], ad[i], bp[j]);
        }
        __syncthreads();
    }

    // Epilogue
    float bv[8];
    #pragma unroll
    for (int j = 0; j < 8; j++) bv[j] = bias[n0 + 8 * tx + j];
    #pragma unroll
    for (int i = 0; i < 8; i++) {
        float out[8];
        #pragma unroll
        for (int j = 0; j < 4; j++) {
            float lo, hi;
            unpack2(acc[i][j], lo, hi);
            out[2 * j]     = lo + bv[2 * j];
            out[2 * j + 1] = hi + bv[2 * j + 1];
        }
        float* cp = &C[(size_t)(m0 + 8 * ty + i) * N + n0 + 8 * tx];
        *(float4*)cp       = make_float4(out[0], out[1], out[2], out[3]);
        *(float4*)(cp + 4) = make_float4(out[4], out[5], out[6], out[7]);
    }
}

// ---------------------------------------------------------------------------
// Strided flash attention, 3 dilation branches in one launch.
//   br0: L=2048, dil=1 ; br1: L=4096, dil=2 ; br2: L=2048, dil=4
// Block = 128 queries x 1 head x 1 branch, 256 threads.
// ty (16) -> 8 q rows each; tx (16) -> 4 keys / 4 d-cols each.
// S kept in registers (FFMA2 packed along q), softmax via shfl over tx lanes,
// P round-trips smem transposed for the PV microkernel. O in registers.
// ---------------------------------------------------------------------------
__global__ __launch_bounds__(256, 2)
void attn_kernel(const float* __restrict__ qkv, float* __restrict__ attn_out)
{
    extern __shared__ float sm[];
    float* Qst = sm;               // [d:64][q:128] pitch 132
    float* Kst = Qst + 64 * 132;   // [d:64][k:64]  pitch 68
    float* Vs  = Kst + 64 * 68;    // [k:64][d:64]  pitch 68
    float* Pt  = Vs  + 64 * 68;    // [k:64][q:128] pitch 132

    const int br = blockIdx.z;
    int L, dil;
    if (br == 0)      { L = 2048; dil = 1; }
    else if (br == 1) { L = 4096; dil = 2; }
    else              { L = 2048; dil = 4; }

    const int q0 = blockIdx.x * 128;
    if (q0 >= L) return;
    const int h   = blockIdx.y;
    const int tid = threadIdx.x;
    const int ty  = tid >> 4;   // 0..15
    const int tx  = tid & 15;   // 0..15

    // Load Q (scaled), transposed into Qst
    {
        const int d  = tid & 63;
        const int qb = tid >> 6;          // 0..3
        #pragma unroll
        for (int i = 0; i < 32; i++) {
            const int q   = qb * 32 + i;
            const int tok = (q0 + q) * dil;
            Qst[d * 132 + q] = qkv[(size_t)tok * QKV3 + h * 64 + d] * QSCALE;
        }
    }

    float mrow[8], lrow[8];
    #pragma unroll
    for (int i = 0; i < 8; i++) { mrow[i] = -1e30f; lrow[i] = 0.0f; }

    ull o[4][4];
    #pragma unroll
    for (int ip = 0; ip < 4; ip++)
        #pragma unroll
        for (int j = 0; j < 4; j++) o[ip][j] = 0ull;

    const int nkt = L >> 6;
    for (int kt = 0; kt < nkt; kt++) {
        __syncthreads();   // previous iteration's readers of Kst/Vs/Pt are done

        // Load K (transposed) and V tiles
        {
            const int d  = tid & 63;
            const int kb = tid >> 6;      // 0..3
            #pragma unroll
            for (int i = 0; i < 16; i++) {
                const int k   = kb * 16 + i;
                const int tok = (kt * 64 + k) * dil;
                const float* base = qkv + (size_t)tok * QKV3 + h * 64 + d;
                Kst[d * 68 + k] = base[768];     // K
                Vs [k * 68 + d] = base[1536];    // V
            }
        }
        __syncthreads();

        // ---- QK^T in registers: s[qpair 4][k 4], packed along q ----
        ull s[4][4];
        #pragma unroll
        for (int ip = 0; ip < 4; ip++)
            #pragma unroll
            for (int j = 0; j < 4; j++) s[ip][j] = 0ull;

        #pragma unroll 4
        for (int d = 0; d < 64; d++) {
            ulonglong2 q01 = *(const ulonglong2*)&Qst[d * 132 + 8 * ty];
            ulonglong2 q23 = *(const ulonglong2*)&Qst[d * 132 + 8 * ty + 4];
            float4 kv = *(const float4*)&Kst[d * 68 + 4 * tx];
            ull qp[4] = { q01.x, q01.y, q23.x, q23.y };
            ull kd[4] = { dup2(kv.x), dup2(kv.y), dup2(kv.z), dup2(kv.w) };
            #pragma unroll
            for (int ip = 0; ip < 4; ip++)
                #pragma unroll
                for (int j = 0; j < 4; j++)
                    ffma2(s[ip][j], qp[ip], kd[j]);
        }

        // Unpack: sr[i][j] = score for row (8*ty+i), key (4*tx+j)
        float sr[8][4];
        #pragma unroll
        for (int ip = 0; ip < 4; ip++)
            #pragma unroll
            for (int j = 0; j < 4; j++)
                unpack2(s[ip][j], sr[2 * ip][j], sr[2 * ip + 1][j]);

        // ---- online softmax: reduce over k (4 local + shfl across 16 tx lanes) ----
        float alpha[8];
        #pragma unroll
        for (int i = 0; i < 8; i++) {
            float mx = fmaxf(fmaxf(sr[i][0], sr[i][1]), fmaxf(sr[i][2], sr[i][3]));
            #pragma unroll
            for (int w = 8; w >= 1; w >>= 1)
                mx = fmaxf(mx, __shfl_xor_sync(0xffffffffu, mx, w));
            const float mnew = fmaxf(mrow[i], mx);
            alpha[i] = __expf(mrow[i] - mnew);
            mrow[i]  = mnew;
            float ls = 0.0f;
            #pragma unroll
            for (int j = 0; j < 4; j++) {
                sr[i][j] = __expf(sr[i][j] - mnew);   // p in place
                ls += sr[i][j];
            }
            #pragma unroll
            for (int w = 8; w >= 1; w >>= 1)
                ls += __shfl_xor_sync(0xffffffffu, ls, w);
            lrow[i] = lrow[i] * alpha[i] + ls;
        }

        // Store P transposed: Pt[k][q]
        #pragma unroll
        for (int j = 0; j < 4; j++) {
            float* pr = &Pt[(4 * tx + j) * 132 + 8 * ty];
            *(float4*)pr       = make_float4(sr[0][j], sr[1][j], sr[2][j], sr[3][j]);
            *(float4*)(pr + 4) = make_float4(sr[4][j], sr[5][j], sr[6][j], sr[7][j]);
        }

        // Rescale O by alpha (packed pairs, same q pairing)
        #pragma unroll
        for (int ip = 0; ip < 4; ip++) {
            ull ap = pack2(alpha[2 * ip], alpha[2 * ip + 1]);
            #pragma unroll
            for (int j = 0; j < 4; j++) fmul2(o[ip][j], ap);
        }
        __syncthreads();   // all P written before PV reads

        // ---- PV: o[qpair][d 4] += Pt * V, packed along q ----
        #pragma unroll 4
        for (int k = 0; k < 64; k++) {
            ulonglong2 p01 = *(const ulonglong2*)&Pt[k * 132 + 8 * ty];
            ulonglong2 p23 = *(const ulonglong2*)&Pt[k * 132 + 8 * ty + 4];
            float4 vv = *(const float4*)&Vs[k * 68 + 4 * tx];
            ull pp[4] = { p01.x, p01.y, p23.x, p23.y };
            ull vd[4] = { dup2(vv.x), dup2(vv.y), dup2(vv.z), dup2(vv.w) };
            #pragma unroll
            for (int ip = 0; ip < 4; ip++)
                #pragma unroll
                for (int j = 0; j < 4; j++)
                    ffma2(o[ip][j], pp[ip], vd[j]);
        }
    }

    // Epilogue: o/l * (1/3), scatter-add into g_attn
    const float w3 = 1.0f / 3.0f;
    #pragma unroll
    for (int ip = 0; ip < 4; ip++) {
        const int   i0   = 2 * ip;
        const int   i1   = 2 * ip + 1;
        const float inv0 = w3 / lrow[i0];
        const float inv1 = w3 / lrow[i1];
        const int   tok0 = (q0 + 8 * ty + i0) * dil;
        const int   tok1 = (q0 + 8 * ty + i1) * dil;
        float* d0 = attn_out + (size_t)tok0 * EMB + h * 64 + 4 * tx;
        float* d1 = attn_out + (size_t)tok1 * EMB + h * 64 + 4 * tx;
        #pragma unroll
        for (int j = 0; j < 4; j++) {
            float v0, v1;
            unpack2(o[ip][j], v0, v1);
            atomicAdd(&d0[j], v0 * inv0);
            atomicAdd(&d1[j], v1 * inv1);
        }
    }
}

// ---------------------------------------------------------------------------
// Launch
// ---------------------------------------------------------------------------
extern "C" void kernel_launch(void* const* d_in, const int* in_sizes, int n_in,
                              void* d_out, int out_size)
{
    const float* x    = (const float*)d_in[0];   // [1,8192,768]
    const float* Wqkv = (const float*)d_in[1];   // [768,2304]
    const float* bqkv = (const float*)d_in[2];   // [2304]
    const float* Wout = (const float*)d_in[3];   // [768,768]
    const float* bout = (const float*)d_in[4];   // [768]
    float*       out  = (float*)d_out;           // [1,8192,768]

    float *qkvp = nullptr, *attnp = nullptr;
    cudaGetSymbolAddress((void**)&qkvp, g_qkv);
    cudaGetSymbolAddress((void**)&attnp, g_attn);

    // Attention dynamic smem: 64*(132+68+68+132)*4 = 102400 bytes
    const int ATTN_SMEM = 102400;
    (void)cudaFuncSetAttribute((const void*)attn_kernel,
                               cudaFuncAttributeMaxDynamicSharedMemorySize, ATTN_SMEM);

    // 1) QKV GEMM: [8192,768] x [768,2304] + bias
    {
        dim3 grid(QKV3 / 128, SEQ / 128);
        gemm_bias_kernel<<<grid, 256>>>(x, Wqkv, bqkv, qkvp, SEQ, QKV3, EMB);
    }

    // 2) Zero the attention accumulator
    cudaMemsetAsync(attnp, 0, (size_t)SEQ * EMB * sizeof(float));

    // 3) All 3 attention branches (grid.x sized for the largest branch)
    {
        dim3 grid(32, NH, 3);
        attn_kernel<<<grid, 256, ATTN_SMEM>>>(qkvp, attnp);
    }

    // 4) Output projection: [8192,768] x [768,768] + bias -> d_out
    {
        dim3 grid(EMB / 128, SEQ / 128);
        gemm_bias_kernel<<<grid, 256>>>(attnp, Wout, bout, out, SEQ, EMB, EMB);
    }
}

// round 7
// speedup vs baseline: 1.5001x; 1.0220x over previous
#include <cuda_runtime.h>
#include <cstdint>

// Problem constants
#define EMB   768
#define NH    12
#define HD    64
#define SEQ   8192
#define QKV3  2304          // 3*EMB
#define QSCALE 0.125f       // 1/sqrt(64)

typedef unsigned long long ull;

// ---------------------------------------------------------------------------
// Packed fp32x2 helpers (sm_100+)
// ---------------------------------------------------------------------------
__device__ __forceinline__ ull dup2(float a) {
    ull d;
    asm("mov.b64 %0, {%1, %1};" : "=l"(d) : "r"(__float_as_uint(a)));
    return d;
}
__device__ __forceinline__ ull pack2(float lo, float hi) {
    ull d;
    asm("mov.b64 %0, {%1, %2};" : "=l"(d) : "r"(__float_as_uint(lo)), "r"(__float_as_uint(hi)));
    return d;
}
__device__ __forceinline__ void unpack2(ull d, float &lo, float &hi) {
    unsigned a, b;
    asm("mov.b64 {%0, %1}, %2;" : "=r"(a), "=r"(b) : "l"(d));
    lo = __uint_as_float(a); hi = __uint_as_float(b);
}
__device__ __forceinline__ void ffma2(ull &d, ull a, ull b) {
    asm("fma.rn.f32x2 %0, %1, %2, %0;" : "+l"(d) : "l"(a), "l"(b));
}
__device__ __forceinline__ void fmul2(ull &d, ull a) {
    asm("mul.rn.f32x2 %0, %0, %1;" : "+l"(d) : "l"(a));
}

// ---------------------------------------------------------------------------
// cp.async helpers
// ---------------------------------------------------------------------------
__device__ __forceinline__ void cp_async16(uint32_t dst, const void* src) {
    asm volatile("cp.async.ca.shared.global [%0], [%1], 16;" :: "r"(dst), "l"(src));
}
__device__ __forceinline__ void cp_async4(uint32_t dst, const void* src) {
    asm volatile("cp.async.ca.shared.global [%0], [%1], 4;" :: "r"(dst), "l"(src));
}
__device__ __forceinline__ void cp_commit() { asm volatile("cp.async.commit_group;"); }
__device__ __forceinline__ void cp_wait0()  { asm volatile("cp.async.wait_group 0;"); }

// ---------------------------------------------------------------------------
// Scratch (device globals — no runtime allocation allowed)
// ---------------------------------------------------------------------------
__device__ float g_qkv[SEQ * QKV3];    // [S][3E] : q +0, k +768, v +1536
__device__ float g_kT [EMB * SEQ];     // [h*64+d][token]  (K transposed)
__device__ float g_attn[SEQ * EMB];    // [S][E]

// ---------------------------------------------------------------------------
// fp32 GEMM + bias: C[M,N] = A[M,K]*B[K,N] + bias[N]
// 128x128 tile, BK=16, 256 threads, 8x8 micro (cols {4tx..+3, 64+4tx..+3}),
// FFMA2 packed along N, 2-stage cp.async pipeline, one sync per tile.
// ---------------------------------------------------------------------------
__global__ __launch_bounds__(256, 2)
void gemm_bias_kernel(const float* __restrict__ A,
                      const float* __restrict__ B,
                      const float* __restrict__ bias,
                      float* __restrict__ C,
                      int M, int N, int K)
{
    __shared__ float As[2][128][20];   // [m][kk] row-major (A reads are ty-broadcast)
    __shared__ float Bs[2][16][132];   // [kk][n]

    const int tid = threadIdx.x;
    const int ty  = tid >> 4;          // 0..15 -> m block of 8
    const int tx  = tid & 15;          // 0..15 -> n cols 4tx and 64+4tx
    const int m0  = blockIdx.y * 128;
    const int n0  = blockIdx.x * 128;

    const uint32_t asB = (uint32_t)__cvta_generic_to_shared(&As[0][0][0]);
    const uint32_t bsB = (uint32_t)__cvta_generic_to_shared(&Bs[0][0][0]);
    const uint32_t asStride = 128 * 20 * 4;
    const uint32_t bsStride = 16 * 132 * 4;

    // cp.async task coords (2 chunks each for A and B per thread)
    const int a_m0 = tid >> 2, a_cc = (tid & 3) * 4;     // +64 rows for i=1
    const int b_k0 = tid >> 5, b_nn = (tid & 31) * 4;    // +8 kk for i=1

    ull acc[8][4];
    #pragma unroll
    for (int i = 0; i < 8; i++)
        #pragma unroll
        for (int j = 0; j < 4; j++) acc[i][j] = 0ull;

    auto copyTile = [&](int k0, int buf) {
        const uint32_t ab = asB + buf * asStride;
        const uint32_t bb = bsB + buf * bsStride;
        #pragma unroll
        for (int i = 0; i < 2; i++) {
            const int m = a_m0 + 64 * i;
            cp_async16(ab + (m * 20 + a_cc) * 4,
                       &A[(size_t)(m0 + m) * K + k0 + a_cc]);
        }
        #pragma unroll
        for (int i = 0; i < 2; i++) {
            const int kk = b_k0 + 8 * i;
            cp_async16(bb + (kk * 132 + b_nn) * 4,
                       &B[(size_t)(k0 + kk) * N + n0 + b_nn]);
        }
    };

    const int T = K >> 4;
    copyTile(0, 0);
    cp_commit();

    for (int it = 0; it < T; it++) {
        cp_wait0();
        __syncthreads();
        if (it + 1 < T) { copyTile((it + 1) << 4, (it + 1) & 1); cp_commit(); }

        const float (*Asb)[20]  = As[it & 1];
        const float (*Bsb)[132] = Bs[it & 1];

        #pragma unroll
        for (int kk2 = 0; kk2 < 8; kk2++) {
            float2 a2[8];
            #pragma unroll
            for (int i = 0; i < 8; i++)
                a2[i] = *(const float2*)&Asb[8 * ty + i][2 * kk2];
            #pragma unroll
            for (int t = 0; t < 2; t++) {
                const int kk = 2 * kk2 + t;
                ulonglong2 bq0 = *(const ulonglong2*)&Bsb[kk][4 * tx];
                ulonglong2 bq1 = *(const ulonglong2*)&Bsb[kk][64 + 4 * tx];
                ull bp[4] = { bq0.x, bq0.y, bq1.x, bq1.y };
                #pragma unroll
                for (int i = 0; i < 8; i++) {
                    ull ad = dup2(t == 0 ? a2[i].x : a2[i].y);
                    #pragma unroll
                    for (int j = 0; j < 4; j++)
                        ffma2(acc[i][j], ad, bp[j]);
                }
            }
        }
    }

    // Epilogue: bias + store (two float4 per row: n0+4tx and n0+64+4tx)
    float bv[8];
    #pragma unroll
    for (int j = 0; j < 4; j++) bv[j]     = bias[n0 + 4 * tx + j];
    #pragma unroll
    for (int j = 0; j < 4; j++) bv[4 + j] = bias[n0 + 64 + 4 * tx + j];
    #pragma unroll
    for (int i = 0; i < 8; i++) {
        float o[8];
        #pragma unroll
        for (int j = 0; j < 4; j++) {
            float lo, hi;
            unpack2(acc[i][j], lo, hi);
            o[2 * j] = lo; o[2 * j + 1] = hi;
        }
        const size_t row = (size_t)(m0 + 8 * ty + i) * N;
        *(float4*)&C[row + n0 + 4 * tx] =
            make_float4(o[0] + bv[0], o[1] + bv[1], o[2] + bv[2], o[3] + bv[3]);
        *(float4*)&C[row + n0 + 64 + 4 * tx] =
            make_float4(o[4] + bv[4], o[5] + bv[5], o[6] + bv[6], o[7] + bv[7]);
    }
}

// ---------------------------------------------------------------------------
// One-shot K transpose: g_kT[c][t] = g_qkv[t][768+c], c in [0,768)
// ---------------------------------------------------------------------------
__global__ void ktrans_kernel(const float* __restrict__ qkv, float* __restrict__ kT)
{
    __shared__ float t[32][33];
    const int x0 = blockIdx.x * 32;   // token
    const int y0 = blockIdx.y * 32;   // channel
    const int tx = threadIdx.x, ty = threadIdx.y;
    #pragma unroll
    for (int i = 0; i < 32; i += 8)
        t[ty + i][tx] = qkv[(size_t)(x0 + ty + i) * QKV3 + 768 + y0 + tx];
    __syncthreads();
    #pragma unroll
    for (int i = 0; i < 32; i += 8)
        kT[(size_t)(y0 + ty + i) * SEQ + x0 + tx] = t[tx][ty + i];
}

// ---------------------------------------------------------------------------
// Strided flash attention, 3 branches in one launch, 2-stage cp.async K/V.
//   br0: L=2048, dil=1 ; br1: L=4096, dil=2 ; br2: L=2048, dil=4
// Block = 128 q x 1 head x 1 branch, 256 threads, 1 CTA/SM (137KB smem).
// ---------------------------------------------------------------------------
__global__ __launch_bounds__(256, 1)
void attn_kernel(const float* __restrict__ qkv,
                 const float* __restrict__ kT,
                 float* __restrict__ attn_out)
{
    extern __shared__ float sm[];
    float* Qst = sm;                        // [d:64][q:128] pitch 132
    float* Kb  = sm + 64 * 132;             // [2][d:64][k:64] pitch 68
    float* Vb  = Kb + 2 * 64 * 68;          // [2][k:64][d:64] pitch 68
    float* Pt  = Vb + 2 * 64 * 68;          // [k:64][q:128] pitch 132

    const uint32_t smB  = (uint32_t)__cvta_generic_to_shared(sm);
    const uint32_t kOff = 64 * 132 * 4;
    const uint32_t vOff = kOff + 2 * 64 * 68 * 4;
    const uint32_t bufB = 64 * 68 * 4;

    const int br = blockIdx.z;
    int L, dil;
    if (br == 0)      { L = 2048; dil = 1; }
    else if (br == 1) { L = 4096; dil = 2; }
    else              { L = 2048; dil = 4; }

    const int q0 = blockIdx.x * 128;
    if (q0 >= L) return;
    const int h   = blockIdx.y;
    const int tid = threadIdx.x;
    const int ty  = tid >> 4;   // 0..15
    const int tx  = tid & 15;   // 0..15

    const float* kTh = kT + (size_t)h * 64 * SEQ;

    auto copyKV = [&](int kt, int buf) {
        const int tok0 = kt * 64;
        const uint32_t kb = smB + kOff + buf * bufB;
        const uint32_t vb = smB + vOff + buf * bufB;
        if (dil == 1) {
            #pragma unroll
            for (int i = 0; i < 4; i++) {
                const int c = tid + 256 * i;
                const int d = c >> 4, cc = (c & 15) * 4;
                cp_async16(kb + (d * 68 + cc) * 4, &kTh[(size_t)d * SEQ + tok0 + cc]);
            }
        } else {
            #pragma unroll
            for (int i = 0; i < 16; i++) {
                const int c = tid + 256 * i;
                const int d = c >> 6, k = c & 63;
                cp_async4(kb + (d * 68 + k) * 4, &kTh[(size_t)d * SEQ + (tok0 + k) * dil]);
            }
        }
        #pragma unroll
        for (int i = 0; i < 4; i++) {
            const int c = tid + 256 * i;
            const int k = c >> 4, cc = (c & 15) * 4;
            cp_async16(vb + (k * 68 + cc) * 4,
                       &qkv[(size_t)(tok0 + k) * dil * QKV3 + 1536 + h * 64 + cc]);
        }
    };

    const int nkt = L >> 6;

    // Prologue: kick off tile 0, then load Q (scaled, transposed) while it flies
    copyKV(0, 0);
    cp_commit();
    {
        const int d4 = (tid & 15) * 4;
        const int qb = tid >> 4;
        #pragma unroll
        for (int i = 0; i < 8; i++) {
            const int q   = qb + 16 * i;
            const int tok = (q0 + q) * dil;
            float4 v = *(const float4*)&qkv[(size_t)tok * QKV3 + h * 64 + d4];
            Qst[(d4 + 0) * 132 + q] = v.x * QSCALE;
            Qst[(d4 + 1) * 132 + q] = v.y * QSCALE;
            Qst[(d4 + 2) * 132 + q] = v.z * QSCALE;
            Qst[(d4 + 3) * 132 + q] = v.w * QSCALE;
        }
    }

    float mrow[8], lrow[8];
    #pragma unroll
    for (int i = 0; i < 8; i++) { mrow[i] = -1e30f; lrow[i] = 0.0f; }

    ull o[4][4];
    #pragma unroll
    for (int ip = 0; ip < 4; ip++)
        #pragma unroll
        for (int j = 0; j < 4; j++) o[ip][j] = 0ull;

    for (int kt = 0; kt < nkt; kt++) {
        cp_wait0();
        __syncthreads();   // K/V[kt] ready; PV(kt-1) done (Pt & old buffers free)
        if (kt + 1 < nkt) { copyKV(kt + 1, (kt + 1) & 1); cp_commit(); }

        const float* Kst = Kb + (kt & 1) * (64 * 68);
        const float* Vs  = Vb + (kt & 1) * (64 * 68);

        // ---- QK^T: s[qpair 4][k 4] packed along q ----
        ull s[4][4];
        #pragma unroll
        for (int ip = 0; ip < 4; ip++)
            #pragma unroll
            for (int j = 0; j < 4; j++) s[ip][j] = 0ull;

        #pragma unroll 4
        for (int d = 0; d < 64; d++) {
            ulonglong2 q01 = *(const ulonglong2*)&Qst[d * 132 + 8 * ty];
            ulonglong2 q23 = *(const ulonglong2*)&Qst[d * 132 + 8 * ty + 4];
            float4 kv = *(const float4*)&Kst[d * 68 + 4 * tx];
            ull qp[4] = { q01.x, q01.y, q23.x, q23.y };
            ull kd[4] = { dup2(kv.x), dup2(kv.y), dup2(kv.z), dup2(kv.w) };
            #pragma unroll
            for (int ip = 0; ip < 4; ip++)
                #pragma unroll
                for (int j = 0; j < 4; j++)
                    ffma2(s[ip][j], qp[ip], kd[j]);
        }

        float sr[8][4];
        #pragma unroll
        for (int ip = 0; ip < 4; ip++)
            #pragma unroll
            for (int j = 0; j < 4; j++)
                unpack2(s[ip][j], sr[2 * ip][j], sr[2 * ip + 1][j]);

        // ---- online softmax (reduce over 4 local + 16 tx lanes via shfl) ----
        float alpha[8];
        #pragma unroll
        for (int i = 0; i < 8; i++) {
            float mx = fmaxf(fmaxf(sr[i][0], sr[i][1]), fmaxf(sr[i][2], sr[i][3]));
            #pragma unroll
            for (int w = 8; w >= 1; w >>= 1)
                mx = fmaxf(mx, __shfl_xor_sync(0xffffffffu, mx, w));
            const float mnew = fmaxf(mrow[i], mx);
            alpha[i] = __expf(mrow[i] - mnew);
            mrow[i]  = mnew;
            float ls = 0.0f;
            #pragma unroll
            for (int j = 0; j < 4; j++) {
                sr[i][j] = __expf(sr[i][j] - mnew);
                ls += sr[i][j];
            }
            #pragma unroll
            for (int w = 8; w >= 1; w >>= 1)
                ls += __shfl_xor_sync(0xffffffffu, ls, w);
            lrow[i] = lrow[i] * alpha[i] + ls;
        }

        // Store P transposed
        #pragma unroll
        for (int j = 0; j < 4; j++) {
            float* pr = &Pt[(4 * tx + j) * 132 + 8 * ty];
            *(float4*)pr       = make_float4(sr[0][j], sr[1][j], sr[2][j], sr[3][j]);
            *(float4*)(pr + 4) = make_float4(sr[4][j], sr[5][j], sr[6][j], sr[7][j]);
        }

        // Rescale O
        #pragma unroll
        for (int ip = 0; ip < 4; ip++) {
            ull ap = pack2(alpha[2 * ip], alpha[2 * ip + 1]);
            #pragma unroll
            for (int j = 0; j < 4; j++) fmul2(o[ip][j], ap);
        }
        __syncthreads();   // Pt visible

        // ---- PV ----
        #pragma unroll 4
        for (int k = 0; k < 64; k++) {
            ulonglong2 p01 = *(const ulonglong2*)&Pt[k * 132 + 8 * ty];
            ulonglong2 p23 = *(const ulonglong2*)&Pt[k * 132 + 8 * ty + 4];
            float4 vv = *(const float4*)&Vs[k * 68 + 4 * tx];
            ull pp[4] = { p01.x, p01.y, p23.x, p23.y };
            ull vd[4] = { dup2(vv.x), dup2(vv.y), dup2(vv.z), dup2(vv.w) };
            #pragma unroll
            for (int ip = 0; ip < 4; ip++)
                #pragma unroll
                for (int j = 0; j < 4; j++)
                    ffma2(o[ip][j], pp[ip], vd[j]);
        }
    }

    // Epilogue: o/l * (1/3), scatter-add
    const float w3 = 1.0f / 3.0f;
    #pragma unroll
    for (int ip = 0; ip < 4; ip++) {
        const int   i0   = 2 * ip, i1 = 2 * ip + 1;
        const float inv0 = w3 / lrow[i0];
        const float inv1 = w3 / lrow[i1];
        float* d0 = attn_out + (size_t)((q0 + 8 * ty + i0) * dil) * EMB + h * 64 + 4 * tx;
        float* d1 = attn_out + (size_t)((q0 + 8 * ty + i1) * dil) * EMB + h * 64 + 4 * tx;
        #pragma unroll
        for (int j = 0; j < 4; j++) {
            float v0, v1;
            unpack2(o[ip][j], v0, v1);
            atomicAdd(&d0[j], v0 * inv0);
            atomicAdd(&d1[j], v1 * inv1);
        }
    }
}

// ---------------------------------------------------------------------------
// Launch
// ---------------------------------------------------------------------------
extern "C" void kernel_launch(void* const* d_in, const int* in_sizes, int n_in,
                              void* d_out, int out_size)
{
    const float* x    = (const float*)d_in[0];
    const float* Wqkv = (const float*)d_in[1];
    const float* bqkv = (const float*)d_in[2];
    const float* Wout = (const float*)d_in[3];
    const float* bout = (const float*)d_in[4];
    float*       out  = (float*)d_out;

    float *qkvp = nullptr, *ktp = nullptr, *attnp = nullptr;
    cudaGetSymbolAddress((void**)&qkvp,  g_qkv);
    cudaGetSymbolAddress((void**)&ktp,   g_kT);
    cudaGetSymbolAddress((void**)&attnp, g_attn);

    const int ATTN_SMEM = (64 * 132 + 2 * 64 * 68 + 2 * 64 * 68 + 64 * 132) * 4; // 137216
    (void)cudaFuncSetAttribute((const void*)attn_kernel,
                               cudaFuncAttributeMaxDynamicSharedMemorySize, ATTN_SMEM);

    // 1) QKV GEMM
    {
        dim3 grid(QKV3 / 128, SEQ / 128);
        gemm_bias_kernel<<<grid, 256>>>(x, Wqkv, bqkv, qkvp, SEQ, QKV3, EMB);
    }

    // 2) K transpose -> g_kT
    {
        dim3 grid(SEQ / 32, EMB / 32);
        ktrans_kernel<<<grid, dim3(32, 8)>>>(qkvp, ktp);
    }

    // 3) Zero attention accumulator
    cudaMemsetAsync(attnp, 0, (size_t)SEQ * EMB * sizeof(float));

    // 4) Attention (all 3 branches)
    {
        dim3 grid(32, NH, 3);
        attn_kernel<<<grid, 256, ATTN_SMEM>>>(qkvp, ktp, attnp);
    }

    // 5) Output projection
    {
        dim3 grid(EMB / 128, SEQ / 128);
        gemm_bias_kernel<<<grid, 256>>>(attnp, Wout, bout, out, SEQ, EMB, EMB);
    }
}

// round 9
// speedup vs baseline: 1.7514x; 1.1675x over previous
#include <cuda_runtime.h>
#include <cuda_bf16.h>
#include <cstdint>

// Problem constants
#define EMB   768
#define NH    12
#define HD    64
#define SEQ   8192
#define QKV3  2304          // 3*EMB
#define QSCALE 0.125f       // 1/sqrt(64)

typedef unsigned long long ull;

// ---------------------------------------------------------------------------
// Packed fp32x2 helpers (attention path)
// ---------------------------------------------------------------------------
__device__ __forceinline__ ull dup2(float a) {
    ull d;
    asm("mov.b64 %0, {%1, %1};" : "=l"(d) : "r"(__float_as_uint(a)));
    return d;
}
__device__ __forceinline__ ull pack2(float lo, float hi) {
    ull d;
    asm("mov.b64 %0, {%1, %2};" : "=l"(d) : "r"(__float_as_uint(lo)), "r"(__float_as_uint(hi)));
    return d;
}
__device__ __forceinline__ void unpack2(ull d, float &lo, float &hi) {
    unsigned a, b;
    asm("mov.b64 {%0, %1}, %2;" : "=r"(a), "=r"(b) : "l"(d));
    lo = __uint_as_float(a); hi = __uint_as_float(b);
}
__device__ __forceinline__ void ffma2(ull &d, ull a, ull b) {
    asm("fma.rn.f32x2 %0, %1, %2, %0;" : "+l"(d) : "l"(a), "l"(b));
}
__device__ __forceinline__ void fmul2(ull &d, ull a) {
    asm("mul.rn.f32x2 %0, %0, %1;" : "+l"(d) : "l"(a));
}

// ---------------------------------------------------------------------------
// cp.async helpers
// ---------------------------------------------------------------------------
__device__ __forceinline__ void cp_async16(uint32_t dst, const void* src) {
    asm volatile("cp.async.ca.shared.global [%0], [%1], 16;" :: "r"(dst), "l"(src));
}
__device__ __forceinline__ void cp_async4(uint32_t dst, const void* src) {
    asm volatile("cp.async.ca.shared.global [%0], [%1], 4;" :: "r"(dst), "l"(src));
}
__device__ __forceinline__ void cp_commit() { asm volatile("cp.async.commit_group;"); }
__device__ __forceinline__ void cp_wait0()  { asm volatile("cp.async.wait_group 0;"); }

// ---------------------------------------------------------------------------
// Tensor-core helpers: ldmatrix + mma.sync (baseline PTX, works on compute_103)
// ---------------------------------------------------------------------------
#define LDSM_X4(r, addr) \
    asm volatile("ldmatrix.sync.aligned.m8n8.x4.shared.b16 {%0,%1,%2,%3}, [%4];" \
        : "=r"((r)[0]), "=r"((r)[1]), "=r"((r)[2]), "=r"((r)[3]) : "r"(addr))

__device__ __forceinline__ void mma16816(float* c, const uint32_t* a,
                                         uint32_t b0, uint32_t b1) {
    asm volatile(
        "mma.sync.aligned.m16n8k16.row.col.f32.bf16.bf16.f32 "
        "{%0,%1,%2,%3}, {%4,%5,%6,%7}, {%8,%9}, {%0,%1,%2,%3};"
        : "+f"(c[0]), "+f"(c[1]), "+f"(c[2]), "+f"(c[3])
        : "r"(a[0]), "r"(a[1]), "r"(a[2]), "r"(a[3]), "r"(b0), "r"(b1));
}

// ---------------------------------------------------------------------------
// Scratch (device globals — no runtime allocation allowed)
// ---------------------------------------------------------------------------
__device__ float g_qkv[SEQ * QKV3];    // [S][3E] : q +0, k +768, v +1536
__device__ float g_kT [EMB * SEQ];     // [h*64+d][token]
__device__ float g_attn[SEQ * EMB];    // [S][E]

__device__ __align__(16) __nv_bfloat16 g_xh[SEQ * EMB];     // x split
__device__ __align__(16) __nv_bfloat16 g_xl[SEQ * EMB];
__device__ __align__(16) __nv_bfloat16 g_ah[SEQ * EMB];     // attn split
__device__ __align__(16) __nv_bfloat16 g_al[SEQ * EMB];
__device__ __align__(16) __nv_bfloat16 g_wqh[QKV3 * EMB];   // Wqkv^T split [N][K]
__device__ __align__(16) __nv_bfloat16 g_wql[QKV3 * EMB];
__device__ __align__(16) __nv_bfloat16 g_woh[EMB * EMB];    // Wout^T split [N][K]
__device__ __align__(16) __nv_bfloat16 g_wol[EMB * EMB];

// ---------------------------------------------------------------------------
// Split fp32 -> (hi, lo) bf16, elementwise (4 elems/thread)
// ---------------------------------------------------------------------------
__global__ void split_kernel(const float* __restrict__ src,
                             __nv_bfloat16* __restrict__ hi,
                             __nv_bfloat16* __restrict__ lo, int n4)
{
    const int i = blockIdx.x * blockDim.x + threadIdx.x;
    if (i >= n4) return;
    float4 v = ((const float4*)src)[i];
    __nv_bfloat16 h0 = __float2bfloat16(v.x), h1 = __float2bfloat16(v.y);
    __nv_bfloat16 h2 = __float2bfloat16(v.z), h3 = __float2bfloat16(v.w);
    __nv_bfloat162* hp = (__nv_bfloat162*)hi;
    __nv_bfloat162* lp = (__nv_bfloat162*)lo;
    hp[2 * i]     = __nv_bfloat162(h0, h1);
    hp[2 * i + 1] = __nv_bfloat162(h2, h3);
    lp[2 * i]     = __nv_bfloat162(__float2bfloat16(v.x - __bfloat162float(h0)),
                                   __float2bfloat16(v.y - __bfloat162float(h1)));
    lp[2 * i + 1] = __nv_bfloat162(__float2bfloat16(v.z - __bfloat162float(h2)),
                                   __float2bfloat16(v.w - __bfloat162float(h3)));
}

// ---------------------------------------------------------------------------
// Transpose + split: W[K][N] fp32 -> T{h,l}[N][K] bf16
// ---------------------------------------------------------------------------
__global__ void wtsplit_kernel(const float* __restrict__ W,
                               __nv_bfloat16* __restrict__ Th,
                               __nv_bfloat16* __restrict__ Tl, int K, int N)
{
    __shared__ float t[32][33];
    const int k0 = blockIdx.x * 32;
    const int n0 = blockIdx.y * 32;
    const int tx = threadIdx.x, ty = threadIdx.y;
    #pragma unroll
    for (int i = 0; i < 32; i += 8)
        t[ty + i][tx] = W[(size_t)(k0 + ty + i) * N + n0 + tx];
    __syncthreads();
    #pragma unroll
    for (int i = 0; i < 32; i += 8) {
        const float v = t[tx][ty + i];
        const __nv_bfloat16 h = __float2bfloat16(v);
        const size_t o = (size_t)(n0 + ty + i) * K + k0 + tx;
        Th[o] = h;
        Tl[o] = __float2bfloat16(v - __bfloat162float(h));
    }
}

// ---------------------------------------------------------------------------
// bf16-split tensor-core GEMM (mma.sync):
//   C[M,N] = (Ah+Al)[M,K] * (Bh+Bl)[N,K]^T + bias  ~= AhBh + AhBl + AlBh
// 128x128 tile, 8 warps (2x4), warp tile 64x32, BK=32, 2-stage cp.async.
// Smem tiles: pitch 40 bf16 (80B) -> conflict-free ldmatrix.
// ---------------------------------------------------------------------------
#define GT_TILE  10240u   // 128 * 40 * 2 bytes
#define GT_STAGE 40960u   // 4 tiles (Ah,Al,Bh,Bl)

__global__ __launch_bounds__(256, 1)
void gemm_mma_kernel(const __nv_bfloat16* __restrict__ Ah,
                     const __nv_bfloat16* __restrict__ Al,
                     const __nv_bfloat16* __restrict__ Bh,
                     const __nv_bfloat16* __restrict__ Bl,
                     const float* __restrict__ bias,
                     float* __restrict__ C,
                     int M, int N, int K)
{
    extern __shared__ char gsm[];
    const uint32_t smB = (uint32_t)__cvta_generic_to_shared(gsm);

    const int tid  = threadIdx.x;
    const int warp = tid >> 5, lane = tid & 31;
    const int wm   = warp >> 2;         // 0..1  (m block of 64)
    const int wn   = warp & 3;          // 0..3  (n block of 32)
    const int m0   = blockIdx.y * 128;
    const int n0   = blockIdx.x * 128;

    float acc[4][4][4];                 // [mt][n8][4]
    #pragma unroll
    for (int a = 0; a < 4; a++)
        #pragma unroll
        for (int b = 0; b < 4; b++)
            #pragma unroll
            for (int c = 0; c < 4; c++) acc[a][b][c] = 0.0f;

    auto copyChunk = [&](int k0c, int buf) {
        const uint32_t sb = smB + (uint32_t)buf * GT_STAGE;
        #pragma unroll
        for (int t = 0; t < 4; t++) {
            const __nv_bfloat16* gp = (t == 0) ? Ah : (t == 1) ? Al : (t == 2) ? Bh : Bl;
            const int base = (t < 2) ? m0 : n0;
            #pragma unroll
            for (int s = 0; s < 2; s++) {
                const int cid = tid + 256 * s;      // 0..511
                const int row = cid >> 2, kc = cid & 3;
                cp_async16(sb + t * GT_TILE + (uint32_t)(row * 40 + kc * 8) * 2,
                           gp + (size_t)(base + row) * K + k0c + kc * 8);
            }
        }
        cp_commit();
    };

    const int T = K >> 5;   // BK=32
    copyChunk(0, 0);

    for (int it = 0; it < T; it++) {
        cp_wait0();
        __syncthreads();
        if (it + 1 < T) copyChunk((it + 1) << 5, (it + 1) & 1);

        const uint32_t stg = smB + (uint32_t)(it & 1) * GT_STAGE;
        const int arow = wm * 64 + (lane & 15);
        const int brow = wn * 32 + (lane & 15);
        const int chi  = (lane >> 4) * 8;

        #pragma unroll
        for (int ks = 0; ks < 2; ks++) {
            const int col = ks * 16 + chi;
            uint32_t a_h[4][4], a_l[4][4];
            #pragma unroll
            for (int mt = 0; mt < 4; mt++) {
                const uint32_t ad = stg + (uint32_t)((arow + mt * 16) * 40 + col) * 2;
                LDSM_X4(a_h[mt], ad);
                LDSM_X4(a_l[mt], ad + GT_TILE);
            }
            uint32_t b_h[2][4], b_l[2][4];
            #pragma unroll
            for (int nt = 0; nt < 2; nt++) {
                const uint32_t bd = stg + 2 * GT_TILE +
                                    (uint32_t)((brow + nt * 16) * 40 + col) * 2;
                LDSM_X4(b_h[nt], bd);
                LDSM_X4(b_l[nt], bd + GT_TILE);
            }
            #pragma unroll
            for (int mt = 0; mt < 4; mt++)
                #pragma unroll
                for (int j = 0; j < 4; j++) {
                    const int nt = j >> 1, hf = j & 1;
                    mma16816(acc[mt][j], a_h[mt], b_h[nt][hf], b_h[nt][hf + 2]);
                    mma16816(acc[mt][j], a_h[mt], b_l[nt][hf], b_l[nt][hf + 2]);
                    mma16816(acc[mt][j], a_l[mt], b_h[nt][hf], b_h[nt][hf + 2]);
                }
        }
    }

    // Epilogue: bias + fp32 store (float2 per fragment row)
    #pragma unroll
    for (int mt = 0; mt < 4; mt++) {
        const int r0 = m0 + wm * 64 + mt * 16 + (lane >> 2);
        #pragma unroll
        for (int j = 0; j < 4; j++) {
            const int cn = n0 + wn * 32 + j * 8 + 2 * (lane & 3);
            const float bx = bias[cn], by = bias[cn + 1];
            *(float2*)&C[(size_t)r0 * N + cn] =
                make_float2(acc[mt][j][0] + bx, acc[mt][j][1] + by);
            *(float2*)&C[(size_t)(r0 + 8) * N + cn] =
                make_float2(acc[mt][j][2] + bx, acc[mt][j][3] + by);
        }
    }
}

// ---------------------------------------------------------------------------
// One-shot K transpose: g_kT[c][t] = g_qkv[t][768+c]
// ---------------------------------------------------------------------------
__global__ void ktrans_kernel(const float* __restrict__ qkv, float* __restrict__ kT)
{
    __shared__ float t[32][33];
    const int x0 = blockIdx.x * 32;   // token
    const int y0 = blockIdx.y * 32;   // channel
    const int tx = threadIdx.x, ty = threadIdx.y;
    #pragma unroll
    for (int i = 0; i < 32; i += 8)
        t[ty + i][tx] = qkv[(size_t)(x0 + ty + i) * QKV3 + 768 + y0 + tx];
    __syncthreads();
    #pragma unroll
    for (int i = 0; i < 32; i += 8)
        kT[(size_t)(y0 + ty + i) * SEQ + x0 + tx] = t[tx][ty + i];
}

// ---------------------------------------------------------------------------
// Strided flash attention (FFMA2 path), 3 branches in one launch.
// ---------------------------------------------------------------------------
__global__ __launch_bounds__(256, 1)
void attn_kernel(const float* __restrict__ qkv,
                 const float* __restrict__ kT,
                 float* __restrict__ attn_out)
{
    extern __shared__ float sm[];
    float* Qst = sm;                        // [d:64][q:128] pitch 132
    float* Kb  = sm + 64 * 132;             // [2][d:64][k:64] pitch 68
    float* Vb  = Kb + 2 * 64 * 68;          // [2][k:64][d:64] pitch 68
    float* Pt  = Vb + 2 * 64 * 68;          // [k:64][q:128] pitch 132

    const uint32_t smB  = (uint32_t)__cvta_generic_to_shared(sm);
    const uint32_t kOff = 64 * 132 * 4;
    const uint32_t vOff = kOff + 2 * 64 * 68 * 4;
    const uint32_t bufB = 64 * 68 * 4;

    const int br = blockIdx.z;
    int L, dil;
    if (br == 0)      { L = 2048; dil = 1; }
    else if (br == 1) { L = 4096; dil = 2; }
    else              { L = 2048; dil = 4; }

    const int q0 = blockIdx.x * 128;
    if (q0 >= L) return;
    const int h   = blockIdx.y;
    const int tid = threadIdx.x;
    const int ty  = tid >> 4;
    const int tx  = tid & 15;

    const float* kTh = kT + (size_t)h * 64 * SEQ;

    auto copyKV = [&](int kt, int buf) {
        const int tok0 = kt * 64;
        const uint32_t kb = smB + kOff + buf * bufB;
        const uint32_t vb = smB + vOff + buf * bufB;
        if (dil == 1) {
            #pragma unroll
            for (int i = 0; i < 4; i++) {
                const int c = tid + 256 * i;
                const int d = c >> 4, cc = (c & 15) * 4;
                cp_async16(kb + (d * 68 + cc) * 4, &kTh[(size_t)d * SEQ + tok0 + cc]);
            }
        } else {
            #pragma unroll
            for (int i = 0; i < 16; i++) {
                const int c = tid + 256 * i;
                const int d = c >> 6, k = c & 63;
                cp_async4(kb + (d * 68 + k) * 4, &kTh[(size_t)d * SEQ + (tok0 + k) * dil]);
            }
        }
        #pragma unroll
        for (int i = 0; i < 4; i++) {
            const int c = tid + 256 * i;
            const int k = c >> 4, cc = (c & 15) * 4;
            cp_async16(vb + (k * 68 + cc) * 4,
                       &qkv[(size_t)(tok0 + k) * dil * QKV3 + 1536 + h * 64 + cc]);
        }
    };

    const int nkt = L >> 6;

    copyKV(0, 0);
    cp_commit();
    {
        const int d4 = (tid & 15) * 4;
        const int qb = tid >> 4;
        #pragma unroll
        for (int i = 0; i < 8; i++) {
            const int q   = qb + 16 * i;
            const int tok = (q0 + q) * dil;
            float4 v = *(const float4*)&qkv[(size_t)tok * QKV3 + h * 64 + d4];
            Qst[(d4 + 0) * 132 + q] = v.x * QSCALE;
            Qst[(d4 + 1) * 132 + q] = v.y * QSCALE;
            Qst[(d4 + 2) * 132 + q] = v.z * QSCALE;
            Qst[(d4 + 3) * 132 + q] = v.w * QSCALE;
        }
    }

    float mrow[8], lrow[8];
    #pragma unroll
    for (int i = 0; i < 8; i++) { mrow[i] = -1e30f; lrow[i] = 0.0f; }

    ull o[4][4];
    #pragma unroll
    for (int ip = 0; ip < 4; ip++)
        #pragma unroll
        for (int j = 0; j < 4; j++) o[ip][j] = 0ull;

    for (int kt = 0; kt < nkt; kt++) {
        cp_wait0();
        __syncthreads();
        if (kt + 1 < nkt) { copyKV(kt + 1, (kt + 1) & 1); cp_commit(); }

        const float* Kst = Kb + (kt & 1) * (64 * 68);
        const float* Vs  = Vb + (kt & 1) * (64 * 68);

        ull s[4][4];
        #pragma unroll
        for (int ip = 0; ip < 4; ip++)
            #pragma unroll
            for (int j = 0; j < 4; j++) s[ip][j] = 0ull;

        #pragma unroll 4
        for (int d = 0; d < 64; d++) {
            ulonglong2 q01 = *(const ulonglong2*)&Qst[d * 132 + 8 * ty];
            ulonglong2 q23 = *(const ulonglong2*)&Qst[d * 132 + 8 * ty + 4];
            float4 kv = *(const float4*)&Kst[d * 68 + 4 * tx];
            ull qp[4] = { q01.x, q01.y, q23.x, q23.y };
            ull kd[4] = { dup2(kv.x), dup2(kv.y), dup2(kv.z), dup2(kv.w) };
            #pragma unroll
            for (int ip = 0; ip < 4; ip++)
                #pragma unroll
                for (int j = 0; j < 4; j++)
                    ffma2(s[ip][j], qp[ip], kd[j]);
        }

        float sr[8][4];
        #pragma unroll
        for (int ip = 0; ip < 4; ip++)
            #pragma unroll
            for (int j = 0; j < 4; j++)
                unpack2(s[ip][j], sr[2 * ip][j], sr[2 * ip + 1][j]);

        float alpha[8];
        #pragma unroll
        for (int i = 0; i < 8; i++) {
            float mx = fmaxf(fmaxf(sr[i][0], sr[i][1]), fmaxf(sr[i][2], sr[i][3]));
            #pragma unroll
            for (int w = 8; w >= 1; w >>= 1)
                mx = fmaxf(mx, __shfl_xor_sync(0xffffffffu, mx, w));
            const float mnew = fmaxf(mrow[i], mx);
            alpha[i] = __expf(mrow[i] - mnew);
            mrow[i]  = mnew;
            float ls = 0.0f;
            #pragma unroll
            for (int j = 0; j < 4; j++) {
                sr[i][j] = __expf(sr[i][j] - mnew);
                ls += sr[i][j];
            }
            #pragma unroll
            for (int w = 8; w >= 1; w >>= 1)
                ls += __shfl_xor_sync(0xffffffffu, ls, w);
            lrow[i] = lrow[i] * alpha[i] + ls;
        }

        #pragma unroll
        for (int j = 0; j < 4; j++) {
            float* pr = &Pt[(4 * tx + j) * 132 + 8 * ty];
            *(float4*)pr       = make_float4(sr[0][j], sr[1][j], sr[2][j], sr[3][j]);
            *(float4*)(pr + 4) = make_float4(sr[4][j], sr[5][j], sr[6][j], sr[7][j]);
        }

        #pragma unroll
        for (int ip = 0; ip < 4; ip++) {
            ull ap = pack2(alpha[2 * ip], alpha[2 * ip + 1]);
            #pragma unroll
            for (int j = 0; j < 4; j++) fmul2(o[ip][j], ap);
        }
        __syncthreads();

        #pragma unroll 4
        for (int k = 0; k < 64; k++) {
            ulonglong2 p01 = *(const ulonglong2*)&Pt[k * 132 + 8 * ty];
            ulonglong2 p23 = *(const ulonglong2*)&Pt[k * 132 + 8 * ty + 4];
            float4 vv = *(const float4*)&Vs[k * 68 + 4 * tx];
            ull pp[4] = { p01.x, p01.y, p23.x, p23.y };
            ull vd[4] = { dup2(vv.x), dup2(vv.y), dup2(vv.z), dup2(vv.w) };
            #pragma unroll
            for (int ip = 0; ip < 4; ip++)
                #pragma unroll
                for (int j = 0; j < 4; j++)
                    ffma2(o[ip][j], pp[ip], vd[j]);
        }
    }

    const float w3 = 1.0f / 3.0f;
    #pragma unroll
    for (int ip = 0; ip < 4; ip++) {
        const int   i0   = 2 * ip, i1 = 2 * ip + 1;
        const float inv0 = w3 / lrow[i0];
        const float inv1 = w3 / lrow[i1];
        float* d0 = attn_out + (size_t)((q0 + 8 * ty + i0) * dil) * EMB + h * 64 + 4 * tx;
        float* d1 = attn_out + (size_t)((q0 + 8 * ty + i1) * dil) * EMB + h * 64 + 4 * tx;
        #pragma unroll
        for (int j = 0; j < 4; j++) {
            float v0, v1;
            unpack2(o[ip][j], v0, v1);
            atomicAdd(&d0[j], v0 * inv0);
            atomicAdd(&d1[j], v1 * inv1);
        }
    }
}

// ---------------------------------------------------------------------------
// Launch
// ---------------------------------------------------------------------------
extern "C" void kernel_launch(void* const* d_in, const int* in_sizes, int n_in,
                              void* d_out, int out_size)
{
    const float* x    = (const float*)d_in[0];
    const float* Wqkv = (const float*)d_in[1];
    const float* bqkv = (const float*)d_in[2];
    const float* Wout = (const float*)d_in[3];
    const float* bout = (const float*)d_in[4];
    float*       out  = (float*)d_out;

    float *qkvp, *ktp, *attnp;
    __nv_bfloat16 *xh, *xl, *ah, *al, *wqh, *wql, *woh, *wol;
    cudaGetSymbolAddress((void**)&qkvp,  g_qkv);
    cudaGetSymbolAddress((void**)&ktp,   g_kT);
    cudaGetSymbolAddress((void**)&attnp, g_attn);
    cudaGetSymbolAddress((void**)&xh,  g_xh);  cudaGetSymbolAddress((void**)&xl,  g_xl);
    cudaGetSymbolAddress((void**)&ah,  g_ah);  cudaGetSymbolAddress((void**)&al,  g_al);
    cudaGetSymbolAddress((void**)&wqh, g_wqh); cudaGetSymbolAddress((void**)&wql, g_wql);
    cudaGetSymbolAddress((void**)&woh, g_woh); cudaGetSymbolAddress((void**)&wol, g_wol);

    const int ATTN_SMEM = (64 * 132 + 2 * 64 * 68 + 2 * 64 * 68 + 64 * 132) * 4; // 137216
    const int GEMM_SMEM = 2 * GT_STAGE;                                           // 81920
    (void)cudaFuncSetAttribute((const void*)attn_kernel,
                               cudaFuncAttributeMaxDynamicSharedMemorySize, ATTN_SMEM);
    (void)cudaFuncSetAttribute((const void*)gemm_mma_kernel,
                               cudaFuncAttributeMaxDynamicSharedMemorySize, GEMM_SMEM);

    // 1) Split inputs to bf16 hi/lo
    split_kernel<<<(SEQ * EMB / 4 + 255) / 256, 256>>>(x, xh, xl, SEQ * EMB / 4);
    wtsplit_kernel<<<dim3(EMB / 32, QKV3 / 32), dim3(32, 8)>>>(Wqkv, wqh, wql, EMB, QKV3);
    wtsplit_kernel<<<dim3(EMB / 32, EMB / 32),  dim3(32, 8)>>>(Wout, woh, wol, EMB, EMB);

    // 2) QKV GEMM (tensor cores, bf16 split)
    {
        dim3 grid(QKV3 / 128, SEQ / 128);
        gemm_mma_kernel<<<grid, 256, GEMM_SMEM>>>(xh, xl, wqh, wql, bqkv, qkvp,
                                                  SEQ, QKV3, EMB);
    }

    // 3) K transpose
    {
        dim3 grid(SEQ / 32, EMB / 32);
        ktrans_kernel<<<grid, dim3(32, 8)>>>(qkvp, ktp);
    }

    // 4) Zero attention accumulator
    cudaMemsetAsync(attnp, 0, (size_t)SEQ * EMB * sizeof(float));

    // 5) Attention (all 3 branches)
    {
        dim3 grid(32, NH, 3);
        attn_kernel<<<grid, 256, ATTN_SMEM>>>(qkvp, ktp, attnp);
    }

    // 6) Split attention output, then output projection (tensor cores)
    split_kernel<<<(SEQ * EMB / 4 + 255) / 256, 256>>>(attnp, ah, al, SEQ * EMB / 4);
    {
        dim3 grid(EMB / 128, SEQ / 128);
        gemm_mma_kernel<<<grid, 256, GEMM_SMEM>>>(ah, al, woh, wol, bout, out,
                                                  SEQ, EMB, EMB);
    }
}

// round 11
// speedup vs baseline: 3.2444x; 1.8524x over previous
#include <cuda_runtime.h>
#include <cuda_bf16.h>
#include <cstdint>

// Problem constants
#define EMB   768
#define NH    12
#define HD    64
#define SEQ   8192
#define QKV3  2304          // 3*EMB
#define QSCALE 0.125f       // 1/sqrt(64)

// ---------------------------------------------------------------------------
// cp.async helpers
// ---------------------------------------------------------------------------
__device__ __forceinline__ void cp_async16(uint32_t dst, const void* src) {
    asm volatile("cp.async.ca.shared.global [%0], [%1], 16;" :: "r"(dst), "l"(src));
}
__device__ __forceinline__ void cp_commit() { asm volatile("cp.async.commit_group;"); }
__device__ __forceinline__ void cp_wait0()  { asm volatile("cp.async.wait_group 0;"); }

// ---------------------------------------------------------------------------
// Tensor-core helpers: ldmatrix + mma.sync (baseline PTX, OK on compute_103)
// ---------------------------------------------------------------------------
#define LDSM_X4(r, addr) \
    asm volatile("ldmatrix.sync.aligned.m8n8.x4.shared.b16 {%0,%1,%2,%3}, [%4];" \
        : "=r"((r)[0]), "=r"((r)[1]), "=r"((r)[2]), "=r"((r)[3]) : "r"(addr))

#define LDSM_X4_T(r, addr) \
    asm volatile("ldmatrix.sync.aligned.m8n8.x4.trans.shared.b16 {%0,%1,%2,%3}, [%4];" \
        : "=r"((r)[0]), "=r"((r)[1]), "=r"((r)[2]), "=r"((r)[3]) : "r"(addr))

__device__ __forceinline__ void mma16816(float* c, const uint32_t* a,
                                         uint32_t b0, uint32_t b1) {
    asm volatile(
        "mma.sync.aligned.m16n8k16.row.col.f32.bf16.bf16.f32 "
        "{%0,%1,%2,%3}, {%4,%5,%6,%7}, {%8,%9}, {%0,%1,%2,%3};"
        : "+f"(c[0]), "+f"(c[1]), "+f"(c[2]), "+f"(c[3])
        : "r"(a[0]), "r"(a[1]), "r"(a[2]), "r"(a[3]), "r"(b0), "r"(b1));
}

// pack two fp32 -> bf16x2 register {a low, b high}
__device__ __forceinline__ uint32_t cvt2_bf16(float a, float b) {
    uint32_t r;
    asm("cvt.rn.bf16x2.f32 %0, %1, %2;" : "=r"(r) : "f"(b), "f"(a));
    return r;
}

// Split (a,b) into bf16 hi pack + bf16 residual pack (in-register 2-term split)
__device__ __forceinline__ void psplit(float a, float b, uint32_t &hi, uint32_t &lo) {
    __nv_bfloat16 ha = __float2bfloat16(a);
    __nv_bfloat16 hb = __float2bfloat16(b);
    __nv_bfloat162 hp = __nv_bfloat162(ha, hb);      // ha low, hb high
    hi = *reinterpret_cast<uint32_t*>(&hp);
    lo = cvt2_bf16(a - __bfloat162float(ha), b - __bfloat162float(hb));
}

// ---------------------------------------------------------------------------
// Scratch (device globals — no runtime allocation allowed)
// ---------------------------------------------------------------------------
__device__ float g_qkv[SEQ * QKV3];    // [S][3E] : q +0, k +768, v +1536
__device__ float g_attn[SEQ * EMB];    // [S][E]

__device__ __align__(16) __nv_bfloat16 g_xh[SEQ * EMB];     // x split
__device__ __align__(16) __nv_bfloat16 g_xl[SEQ * EMB];
__device__ __align__(16) __nv_bfloat16 g_ah[SEQ * EMB];     // attn split
__device__ __align__(16) __nv_bfloat16 g_al[SEQ * EMB];
__device__ __align__(16) __nv_bfloat16 g_wqh[QKV3 * EMB];   // Wqkv^T split [N][K]
__device__ __align__(16) __nv_bfloat16 g_wql[QKV3 * EMB];
__device__ __align__(16) __nv_bfloat16 g_woh[EMB * EMB];    // Wout^T split [N][K]
__device__ __align__(16) __nv_bfloat16 g_wol[EMB * EMB];

__device__ __align__(16) __nv_bfloat16 g_kh[NH * SEQ * HD]; // K split, [h][tok][d]
__device__ __align__(16) __nv_bfloat16 g_kl[NH * SEQ * HD];
__device__ __align__(16) __nv_bfloat16 g_vh[NH * SEQ * HD]; // V split, [h][tok][d]
__device__ __align__(16) __nv_bfloat16 g_vl[NH * SEQ * HD];

// ---------------------------------------------------------------------------
// Split fp32 -> (hi, lo) bf16, elementwise (4 elems/thread)
// ---------------------------------------------------------------------------
__global__ void split_kernel(const float* __restrict__ src,
                             __nv_bfloat16* __restrict__ hi,
                             __nv_bfloat16* __restrict__ lo, int n4)
{
    const int i = blockIdx.x * blockDim.x + threadIdx.x;
    if (i >= n4) return;
    float4 v = ((const float4*)src)[i];
    __nv_bfloat16 h0 = __float2bfloat16(v.x), h1 = __float2bfloat16(v.y);
    __nv_bfloat16 h2 = __float2bfloat16(v.z), h3 = __float2bfloat16(v.w);
    __nv_bfloat162* hp = (__nv_bfloat162*)hi;
    __nv_bfloat162* lp = (__nv_bfloat162*)lo;
    hp[2 * i]     = __nv_bfloat162(h0, h1);
    hp[2 * i + 1] = __nv_bfloat162(h2, h3);
    lp[2 * i]     = __nv_bfloat162(__float2bfloat16(v.x - __bfloat162float(h0)),
                                   __float2bfloat16(v.y - __bfloat162float(h1)));
    lp[2 * i + 1] = __nv_bfloat162(__float2bfloat16(v.z - __bfloat162float(h2)),
                                   __float2bfloat16(v.w - __bfloat162float(h3)));
}

// ---------------------------------------------------------------------------
// Transpose + split: W[K][N] fp32 -> T{h,l}[N][K] bf16
// ---------------------------------------------------------------------------
__global__ void wtsplit_kernel(const float* __restrict__ W,
                               __nv_bfloat16* __restrict__ Th,
                               __nv_bfloat16* __restrict__ Tl, int K, int N)
{
    __shared__ float t[32][33];
    const int k0 = blockIdx.x * 32;
    const int n0 = blockIdx.y * 32;
    const int tx = threadIdx.x, ty = threadIdx.y;
    #pragma unroll
    for (int i = 0; i < 32; i += 8)
        t[ty + i][tx] = W[(size_t)(k0 + ty + i) * N + n0 + tx];
    __syncthreads();
    #pragma unroll
    for (int i = 0; i < 32; i += 8) {
        const float v = t[tx][ty + i];
        const __nv_bfloat16 h = __float2bfloat16(v);
        const size_t o = (size_t)(n0 + ty + i) * K + k0 + tx;
        Th[o] = h;
        Tl[o] = __float2bfloat16(v - __bfloat162float(h));
    }
}

// ---------------------------------------------------------------------------
// K/V prep: split K and V to bf16 hi/lo, per-head layout [h][tok][64].
// Grid: SEQ blocks x 192 threads (each thread: 4 K + 4 V elems).
// ---------------------------------------------------------------------------
__global__ void kvsplit_kernel(const float* __restrict__ qkv,
                               __nv_bfloat16* __restrict__ kh,
                               __nv_bfloat16* __restrict__ kl,
                               __nv_bfloat16* __restrict__ vh,
                               __nv_bfloat16* __restrict__ vl)
{
    const int t = blockIdx.x;
    const int i = threadIdx.x;               // 0..191
    const int h = (4 * i) >> 6, d = (4 * i) & 63;
    const size_t o = ((size_t)h * SEQ + t) * HD + d;

    float4 kv = *(const float4*)&qkv[(size_t)t * QKV3 + 768 + 4 * i];
    {
        __nv_bfloat16 h0 = __float2bfloat16(kv.x), h1 = __float2bfloat16(kv.y);
        __nv_bfloat16 h2 = __float2bfloat16(kv.z), h3 = __float2bfloat16(kv.w);
        *(__nv_bfloat162*)&kh[o]     = __nv_bfloat162(h0, h1);
        *(__nv_bfloat162*)&kh[o + 2] = __nv_bfloat162(h2, h3);
        *(__nv_bfloat162*)&kl[o] =
            __nv_bfloat162(__float2bfloat16(kv.x - __bfloat162float(h0)),
                           __float2bfloat16(kv.y - __bfloat162float(h1)));
        *(__nv_bfloat162*)&kl[o + 2] =
            __nv_bfloat162(__float2bfloat16(kv.z - __bfloat162float(h2)),
                           __float2bfloat16(kv.w - __bfloat162float(h3)));
    }

    float4 vv = *(const float4*)&qkv[(size_t)t * QKV3 + 1536 + 4 * i];
    {
        __nv_bfloat16 h0 = __float2bfloat16(vv.x), h1 = __float2bfloat16(vv.y);
        __nv_bfloat16 h2 = __float2bfloat16(vv.z), h3 = __float2bfloat16(vv.w);
        *(__nv_bfloat162*)&vh[o]     = __nv_bfloat162(h0, h1);
        *(__nv_bfloat162*)&vh[o + 2] = __nv_bfloat162(h2, h3);
        *(__nv_bfloat162*)&vl[o] =
            __nv_bfloat162(__float2bfloat16(vv.x - __bfloat162float(h0)),
                           __float2bfloat16(vv.y - __bfloat162float(h1)));
        *(__nv_bfloat162*)&vl[o + 2] =
            __nv_bfloat162(__float2bfloat16(vv.z - __bfloat162float(h2)),
                           __float2bfloat16(vv.w - __bfloat162float(h3)));
    }
}

// ---------------------------------------------------------------------------
// bf16-split tensor-core GEMM (unchanged — proven)
// ---------------------------------------------------------------------------
#define GT_TILE  10240u   // 128 * 40 * 2 bytes
#define GT_STAGE 40960u   // 4 tiles (Ah,Al,Bh,Bl)

__global__ __launch_bounds__(256, 1)
void gemm_mma_kernel(const __nv_bfloat16* __restrict__ Ah,
                     const __nv_bfloat16* __restrict__ Al,
                     const __nv_bfloat16* __restrict__ Bh,
                     const __nv_bfloat16* __restrict__ Bl,
                     const float* __restrict__ bias,
                     float* __restrict__ C,
                     int M, int N, int K)
{
    extern __shared__ char gsm[];
    const uint32_t smB = (uint32_t)__cvta_generic_to_shared(gsm);

    const int tid  = threadIdx.x;
    const int warp = tid >> 5, lane = tid & 31;
    const int wm   = warp >> 2;
    const int wn   = warp & 3;
    const int m0   = blockIdx.y * 128;
    const int n0   = blockIdx.x * 128;

    float acc[4][4][4];
    #pragma unroll
    for (int a = 0; a < 4; a++)
        #pragma unroll
        for (int b = 0; b < 4; b++)
            #pragma unroll
            for (int c = 0; c < 4; c++) acc[a][b][c] = 0.0f;

    auto copyChunk = [&](int k0c, int buf) {
        const uint32_t sb = smB + (uint32_t)buf * GT_STAGE;
        #pragma unroll
        for (int t = 0; t < 4; t++) {
            const __nv_bfloat16* gp = (t == 0) ? Ah : (t == 1) ? Al : (t == 2) ? Bh : Bl;
            const int base = (t < 2) ? m0 : n0;
            #pragma unroll
            for (int s = 0; s < 2; s++) {
                const int cid = tid + 256 * s;
                const int row = cid >> 2, kc = cid & 3;
                cp_async16(sb + t * GT_TILE + (uint32_t)(row * 40 + kc * 8) * 2,
                           gp + (size_t)(base + row) * K + k0c + kc * 8);
            }
        }
        cp_commit();
    };

    const int T = K >> 5;
    copyChunk(0, 0);

    for (int it = 0; it < T; it++) {
        cp_wait0();
        __syncthreads();
        if (it + 1 < T) copyChunk((it + 1) << 5, (it + 1) & 1);

        const uint32_t stg = smB + (uint32_t)(it & 1) * GT_STAGE;
        const int arow = wm * 64 + (lane & 15);
        const int brow = wn * 32 + (lane & 15);
        const int chi  = (lane >> 4) * 8;

        #pragma unroll
        for (int ks = 0; ks < 2; ks++) {
            const int col = ks * 16 + chi;
            uint32_t a_h[4][4], a_l[4][4];
            #pragma unroll
            for (int mt = 0; mt < 4; mt++) {
                const uint32_t ad = stg + (uint32_t)((arow + mt * 16) * 40 + col) * 2;
                LDSM_X4(a_h[mt], ad);
                LDSM_X4(a_l[mt], ad + GT_TILE);
            }
            uint32_t b_h[2][4], b_l[2][4];
            #pragma unroll
            for (int nt = 0; nt < 2; nt++) {
                const uint32_t bd = stg + 2 * GT_TILE +
                                    (uint32_t)((brow + nt * 16) * 40 + col) * 2;
                LDSM_X4(b_h[nt], bd);
                LDSM_X4(b_l[nt], bd + GT_TILE);
            }
            #pragma unroll
            for (int mt = 0; mt < 4; mt++)
                #pragma unroll
                for (int j = 0; j < 4; j++) {
                    const int nt = j >> 1, hf = j & 1;
                    mma16816(acc[mt][j], a_h[mt], b_h[nt][hf], b_h[nt][hf + 2]);
                    mma16816(acc[mt][j], a_h[mt], b_l[nt][hf], b_l[nt][hf + 2]);
                    mma16816(acc[mt][j], a_l[mt], b_h[nt][hf], b_h[nt][hf + 2]);
                }
        }
    }

    #pragma unroll
    for (int mt = 0; mt < 4; mt++) {
        const int r0 = m0 + wm * 64 + mt * 16 + (lane >> 2);
        #pragma unroll
        for (int j = 0; j < 4; j++) {
            const int cn = n0 + wn * 32 + j * 8 + 2 * (lane & 3);
            const float bx = bias[cn], by = bias[cn + 1];
            *(float2*)&C[(size_t)r0 * N + cn] =
                make_float2(acc[mt][j][0] + bx, acc[mt][j][1] + by);
            *(float2*)&C[(size_t)(r0 + 8) * N + cn] =
                make_float2(acc[mt][j][2] + bx, acc[mt][j][3] + by);
        }
    }
}

// ---------------------------------------------------------------------------
// Tensor-core strided flash attention, 3 branches in one launch.
// Block = 128 q x 1 head x 1 branch, 256 threads (8 warps x 16q).
// QK^T: 3-term bf16 split; PV: 3-term split too (P split in registers).
// ---------------------------------------------------------------------------
#define AP 72                       // smem pitch (bf16 elems)
#define A_QL   18432u               // 128*72*2
#define A_K    36864u               // K: [buf]{Kh,Kl} 9216B tiles, 18432B/buf
#define A_V    73728u               // V: [buf]{Vh,Vl} 9216B tiles, 18432B/buf
#define A_SMEM 110592u

__global__ __launch_bounds__(256)
void attn_mma_kernel(const float* __restrict__ qkv,
                     const __nv_bfloat16* __restrict__ kh,
                     const __nv_bfloat16* __restrict__ kl,
                     const __nv_bfloat16* __restrict__ vh,
                     const __nv_bfloat16* __restrict__ vl,
                     float* __restrict__ attn_out)
{
    extern __shared__ char asm_[];
    const uint32_t smB = (uint32_t)__cvta_generic_to_shared(asm_);

    const int br = blockIdx.z;
    int L, dil;
    if (br == 0)      { L = 2048; dil = 1; }
    else if (br == 1) { L = 4096; dil = 2; }
    else              { L = 2048; dil = 4; }

    const int q0 = blockIdx.x * 128;
    if (q0 >= L) return;
    const int h    = blockIdx.y;
    const int tid  = threadIdx.x;
    const int warp = tid >> 5, lane = tid & 31;

    const size_t hoff = (size_t)h * SEQ * HD;

    auto copyKV = [&](int kt, int buf) {
        const int tok0 = kt * 64;
        const uint32_t kb = smB + A_K + (uint32_t)buf * 18432u;
        const uint32_t vbuf = smB + A_V + (uint32_t)buf * 18432u;
        #pragma unroll
        for (int i = 0; i < 8; i++) {
            const int flat = tid + 256 * i;          // 0..2047
            const int sel  = flat >> 9;              // 0:Kh 1:Kl 2:Vh 3:Vl
            const int r    = (flat >> 3) & 63;
            const int c    = flat & 7;
            const size_t src = hoff + (size_t)(tok0 + r) * dil * HD + c * 8;
            const uint32_t doff = (uint32_t)(r * AP + c * 8) * 2;
            const __nv_bfloat16* gp = (sel == 0) ? kh : (sel == 1) ? kl
                                     : (sel == 2) ? vh : vl;
            const uint32_t db = (sel == 0) ? kb : (sel == 1) ? kb + 9216u
                               : (sel == 2) ? vbuf : vbuf + 9216u;
            cp_async16(db + doff, gp + src);
        }
        cp_commit();
    };

    const int nkt = L >> 6;

    // Prologue: start K/V tile 0, stage Q (scaled + split) into smem
    copyKV(0, 0);
    {
        const int qr = tid >> 1, qc0 = (tid & 1) * 32;
        const float* qsrc = qkv + (size_t)(q0 + qr) * dil * QKV3 + h * 64 + qc0;
        __nv_bfloat16* Qh = (__nv_bfloat16*)asm_;
        __nv_bfloat16* Ql = Qh + 128 * AP;
        #pragma unroll
        for (int i = 0; i < 8; i++) {
            float4 v = *(const float4*)&qsrc[4 * i];
            v.x *= QSCALE; v.y *= QSCALE; v.z *= QSCALE; v.w *= QSCALE;
            __nv_bfloat16 h0 = __float2bfloat16(v.x), h1 = __float2bfloat16(v.y);
            __nv_bfloat16 h2 = __float2bfloat16(v.z), h3 = __float2bfloat16(v.w);
            const int o = qr * AP + qc0 + 4 * i;
            *(__nv_bfloat162*)&Qh[o]     = __nv_bfloat162(h0, h1);
            *(__nv_bfloat162*)&Qh[o + 2] = __nv_bfloat162(h2, h3);
            *(__nv_bfloat162*)&Ql[o] =
                __nv_bfloat162(__float2bfloat16(v.x - __bfloat162float(h0)),
                               __float2bfloat16(v.y - __bfloat162float(h1)));
            *(__nv_bfloat162*)&Ql[o + 2] =
                __nv_bfloat162(__float2bfloat16(v.z - __bfloat162float(h2)),
                               __float2bfloat16(v.w - __bfloat162float(h3)));
        }
    }
    __syncthreads();

    // Per-warp Q fragments (held in registers for the whole block)
    uint32_t qfh[4][4], qfl[4][4];
    {
        const int qrow = 16 * warp + (lane & 15);
        #pragma unroll
        for (int ks = 0; ks < 4; ks++) {
            const uint32_t ad = smB + (uint32_t)(qrow * AP + ks * 16 + (lane >> 4) * 8) * 2;
            LDSM_X4(qfh[ks], ad);
            LDSM_X4(qfl[ks], ad + A_QL);
        }
    }

    float o[8][4];
    #pragma unroll
    for (int j = 0; j < 8; j++)
        #pragma unroll
        for (int c = 0; c < 4; c++) o[j][c] = 0.0f;
    float mrA = -1e30f, mrB = -1e30f, lrA = 0.0f, lrB = 0.0f;

    for (int kt = 0; kt < nkt; kt++) {
        cp_wait0();
        __syncthreads();
        if (kt + 1 < nkt) copyKV(kt + 1, (kt + 1) & 1);

        const int buf = kt & 1;
        const uint32_t kbase = smB + A_K + (uint32_t)buf * 18432u;
        const uint32_t vbase = smB + A_V + (uint32_t)buf * 18432u;

        // ---- S = Q K^T (3 split terms), accumulators in registers ----
        float s[8][4];
        #pragma unroll
        for (int j = 0; j < 8; j++)
            #pragma unroll
            for (int c = 0; c < 4; c++) s[j][c] = 0.0f;

        #pragma unroll
        for (int ks = 0; ks < 4; ks++) {
            uint32_t khf[4][4], klf[4][4];
            #pragma unroll
            for (int g = 0; g < 4; g++) {
                const uint32_t ad = kbase +
                    (uint32_t)((g * 16 + (lane & 15)) * AP + ks * 16 + (lane >> 4) * 8) * 2;
                LDSM_X4(khf[g], ad);
                LDSM_X4(klf[g], ad + 9216u);
            }
            #pragma unroll
            for (int g = 0; g < 4; g++) {
                mma16816(s[2 * g],     qfh[ks], khf[g][0], khf[g][2]);
                mma16816(s[2 * g + 1], qfh[ks], khf[g][1], khf[g][3]);
                mma16816(s[2 * g],     qfh[ks], klf[g][0], klf[g][2]);
                mma16816(s[2 * g + 1], qfh[ks], klf[g][1], klf[g][3]);
                mma16816(s[2 * g],     qfl[ks], khf[g][0], khf[g][2]);
                mma16816(s[2 * g + 1], qfl[ks], khf[g][1], khf[g][3]);
            }
        }

        // ---- online softmax (rows rA = lane>>2, rB = rA+8; quad shfl) ----
        float mA = -1e30f, mB = -1e30f;
        #pragma unroll
        for (int j = 0; j < 8; j++) {
            mA = fmaxf(mA, fmaxf(s[j][0], s[j][1]));
            mB = fmaxf(mB, fmaxf(s[j][2], s[j][3]));
        }
        mA = fmaxf(mA, __shfl_xor_sync(0xffffffffu, mA, 1));
        mA = fmaxf(mA, __shfl_xor_sync(0xffffffffu, mA, 2));
        mB = fmaxf(mB, __shfl_xor_sync(0xffffffffu, mB, 1));
        mB = fmaxf(mB, __shfl_xor_sync(0xffffffffu, mB, 2));

        const float mnA = fmaxf(mrA, mA), mnB = fmaxf(mrB, mB);
        const float alA = __expf(mrA - mnA), alB = __expf(mrB - mnB);
        mrA = mnA; mrB = mnB;

        float lsA = 0.0f, lsB = 0.0f;
        #pragma unroll
        for (int j = 0; j < 8; j++) {
            s[j][0] = __expf(s[j][0] - mnA);
            s[j][1] = __expf(s[j][1] - mnA);
            s[j][2] = __expf(s[j][2] - mnB);
            s[j][3] = __expf(s[j][3] - mnB);
            lsA += s[j][0] + s[j][1];
            lsB += s[j][2] + s[j][3];
        }
        lsA += __shfl_xor_sync(0xffffffffu, lsA, 1);
        lsA += __shfl_xor_sync(0xffffffffu, lsA, 2);
        lsB += __shfl_xor_sync(0xffffffffu, lsB, 1);
        lsB += __shfl_xor_sync(0xffffffffu, lsB, 2);
        lrA = lrA * alA + lsA;
        lrB = lrB * alB + lsB;

        // rescale O
        #pragma unroll
        for (int j = 0; j < 8; j++) {
            o[j][0] *= alA; o[j][1] *= alA;
            o[j][2] *= alB; o[j][3] *= alB;
        }

        // ---- O += P V  (P split in registers; V split in smem; 3 terms) ----
        #pragma unroll
        for (int t = 0; t < 4; t++) {
            uint32_t pah[4], pal[4];
            psplit(s[2 * t][0],     s[2 * t][1],     pah[0], pal[0]);
            psplit(s[2 * t][2],     s[2 * t][3],     pah[1], pal[1]);
            psplit(s[2 * t + 1][0], s[2 * t + 1][1], pah[2], pal[2]);
            psplit(s[2 * t + 1][2], s[2 * t + 1][3], pah[3], pal[3]);
            #pragma unroll
            for (int g = 0; g < 4; g++) {
                uint32_t vfh[4], vfl[4];
                const uint32_t ad = vbase +
                    (uint32_t)((16 * t + ((lane >> 3) & 1) * 8 + (lane & 7)) * AP +
                               16 * g + (lane >> 4) * 8) * 2;
                LDSM_X4_T(vfh, ad);
                LDSM_X4_T(vfl, ad + 9216u);
                mma16816(o[2 * g],     pah, vfh[0], vfh[1]);
                mma16816(o[2 * g + 1], pah, vfh[2], vfh[3]);
                mma16816(o[2 * g],     pah, vfl[0], vfl[1]);
                mma16816(o[2 * g + 1], pah, vfl[2], vfl[3]);
                mma16816(o[2 * g],     pal, vfh[0], vfh[1]);
                mma16816(o[2 * g + 1], pal, vfh[2], vfh[3]);
            }
        }
    }

    // Epilogue: o/l * (1/3), scatter-add
    const float w3 = 1.0f / 3.0f;
    const float invA = w3 / lrA, invB = w3 / lrB;
    const int rA = q0 + 16 * warp + (lane >> 2);
    float* baseA = attn_out + (size_t)rA * dil * EMB + h * 64;
    float* baseB = attn_out + (size_t)(rA + 8) * dil * EMB + h * 64;
    #pragma unroll
    for (int j = 0; j < 8; j++) {
        const int c = 8 * j + 2 * (lane & 3);
        atomicAdd(baseA + c,     o[j][0] * invA);
        atomicAdd(baseA + c + 1, o[j][1] * invA);
        atomicAdd(baseB + c,     o[j][2] * invB);
        atomicAdd(baseB + c + 1, o[j][3] * invB);
    }
}

// ---------------------------------------------------------------------------
// Launch
// ---------------------------------------------------------------------------
extern "C" void kernel_launch(void* const* d_in, const int* in_sizes, int n_in,
                              void* d_out, int out_size)
{
    const float* x    = (const float*)d_in[0];
    const float* Wqkv = (const float*)d_in[1];
    const float* bqkv = (const float*)d_in[2];
    const float* Wout = (const float*)d_in[3];
    const float* bout = (const float*)d_in[4];
    float*       out  = (float*)d_out;

    float *qkvp, *attnp;
    __nv_bfloat16 *xh, *xl, *ah, *al, *wqh, *wql, *woh, *wol, *khp, *klp, *vhp, *vlp;
    cudaGetSymbolAddress((void**)&qkvp,  g_qkv);
    cudaGetSymbolAddress((void**)&attnp, g_attn);
    cudaGetSymbolAddress((void**)&xh,  g_xh);  cudaGetSymbolAddress((void**)&xl,  g_xl);
    cudaGetSymbolAddress((void**)&ah,  g_ah);  cudaGetSymbolAddress((void**)&al,  g_al);
    cudaGetSymbolAddress((void**)&wqh, g_wqh); cudaGetSymbolAddress((void**)&wql, g_wql);
    cudaGetSymbolAddress((void**)&woh, g_woh); cudaGetSymbolAddress((void**)&wol, g_wol);
    cudaGetSymbolAddress((void**)&khp, g_kh);  cudaGetSymbolAddress((void**)&klp, g_kl);
    cudaGetSymbolAddress((void**)&vhp, g_vh);  cudaGetSymbolAddress((void**)&vlp, g_vl);

    const int GEMM_SMEM = 2 * GT_STAGE;   // 81920
    (void)cudaFuncSetAttribute((const void*)gemm_mma_kernel,
                               cudaFuncAttributeMaxDynamicSharedMemorySize, GEMM_SMEM);
    (void)cudaFuncSetAttribute((const void*)attn_mma_kernel,
                               cudaFuncAttributeMaxDynamicSharedMemorySize, A_SMEM);

    // 1) Split inputs to bf16 hi/lo
    split_kernel<<<(SEQ * EMB / 4 + 255) / 256, 256>>>(x, xh, xl, SEQ * EMB / 4);
    wtsplit_kernel<<<dim3(EMB / 32, QKV3 / 32), dim3(32, 8)>>>(Wqkv, wqh, wql, EMB, QKV3);
    wtsplit_kernel<<<dim3(EMB / 32, EMB / 32),  dim3(32, 8)>>>(Wout, woh, wol, EMB, EMB);

    // 2) QKV GEMM (tensor cores, bf16 split)
    {
        dim3 grid(QKV3 / 128, SEQ / 128);
        gemm_mma_kernel<<<grid, 256, GEMM_SMEM>>>(xh, xl, wqh, wql, bqkv, qkvp,
                                                  SEQ, QKV3, EMB);
    }

    // 3) K/V split to per-head bf16 hi/lo
    kvsplit_kernel<<<SEQ, 192>>>(qkvp, khp, klp, vhp, vlp);

    // 4) Zero attention accumulator
    cudaMemsetAsync(attnp, 0, (size_t)SEQ * EMB * sizeof(float));

    // 5) Attention (tensor cores, all 3 branches)
    {
        dim3 grid(32, NH, 3);
        attn_mma_kernel<<<grid, 256, A_SMEM>>>(qkvp, khp, klp, vhp, vlp, attnp);
    }

    // 6) Split attention output, then output projection (tensor cores)
    split_kernel<<<(SEQ * EMB / 4 + 255) / 256, 256>>>(attnp, ah, al, SEQ * EMB / 4);
    {
        dim3 grid(EMB / 128, SEQ / 128);
        gemm_mma_kernel<<<grid, 256, GEMM_SMEM>>>(ah, al, woh, wol, bout, out,
                                                  SEQ, EMB, EMB);
    }
}

// round 12
// speedup vs baseline: 3.5330x; 1.0890x over previous
#include <cuda_runtime.h>
#include <cuda_bf16.h>
#include <cstdint>

// Problem constants
#define EMB   768
#define NH    12
#define HD    64
#define SEQ   8192
#define QKV3  2304          // 3*EMB
#define QSCALE 0.125f       // 1/sqrt(64)

// ---------------------------------------------------------------------------
// cp.async helpers
// ---------------------------------------------------------------------------
__device__ __forceinline__ void cp_async16(uint32_t dst, const void* src) {
    asm volatile("cp.async.ca.shared.global [%0], [%1], 16;" :: "r"(dst), "l"(src));
}
__device__ __forceinline__ void cp_commit() { asm volatile("cp.async.commit_group;"); }
__device__ __forceinline__ void cp_wait0()  { asm volatile("cp.async.wait_group 0;"); }

// ---------------------------------------------------------------------------
// Tensor-core helpers: ldmatrix + mma.sync (baseline PTX, OK on compute_103)
// ---------------------------------------------------------------------------
#define LDSM_X4(r, addr) \
    asm volatile("ldmatrix.sync.aligned.m8n8.x4.shared.b16 {%0,%1,%2,%3}, [%4];" \
        : "=r"((r)[0]), "=r"((r)[1]), "=r"((r)[2]), "=r"((r)[3]) : "r"(addr))

#define LDSM_X4_T(r, addr) \
    asm volatile("ldmatrix.sync.aligned.m8n8.x4.trans.shared.b16 {%0,%1,%2,%3}, [%4];" \
        : "=r"((r)[0]), "=r"((r)[1]), "=r"((r)[2]), "=r"((r)[3]) : "r"(addr))

__device__ __forceinline__ void mma16816(float* c, const uint32_t* a,
                                         uint32_t b0, uint32_t b1) {
    asm volatile(
        "mma.sync.aligned.m16n8k16.row.col.f32.bf16.bf16.f32 "
        "{%0,%1,%2,%3}, {%4,%5,%6,%7}, {%8,%9}, {%0,%1,%2,%3};"
        : "+f"(c[0]), "+f"(c[1]), "+f"(c[2]), "+f"(c[3])
        : "r"(a[0]), "r"(a[1]), "r"(a[2]), "r"(a[3]), "r"(b0), "r"(b1));
}

// pack two fp32 -> bf16x2 register {a low, b high}
__device__ __forceinline__ uint32_t cvt2_bf16(float a, float b) {
    uint32_t r;
    asm("cvt.rn.bf16x2.f32 %0, %1, %2;" : "=r"(r) : "f"(b), "f"(a));
    return r;
}

// Split (a,b) into bf16 hi pack + bf16 residual pack (in-register 2-term split)
__device__ __forceinline__ void psplit(float a, float b, uint32_t &hi, uint32_t &lo) {
    __nv_bfloat16 ha = __float2bfloat16(a);
    __nv_bfloat16 hb = __float2bfloat16(b);
    __nv_bfloat162 hp = __nv_bfloat162(ha, hb);      // ha low, hb high
    hi = *reinterpret_cast<uint32_t*>(&hp);
    lo = cvt2_bf16(a - __bfloat162float(ha), b - __bfloat162float(hb));
}

// ---------------------------------------------------------------------------
// Scratch (device globals — no runtime allocation allowed)
// ---------------------------------------------------------------------------
__device__ float g_qkv[SEQ * QKV3];    // [S][3E] : q +0, k +768, v +1536
__device__ float g_attn[SEQ * EMB];    // [S][E]

__device__ __align__(16) __nv_bfloat16 g_xh[SEQ * EMB];     // x split
__device__ __align__(16) __nv_bfloat16 g_xl[SEQ * EMB];
__device__ __align__(16) __nv_bfloat16 g_ah[SEQ * EMB];     // attn split
__device__ __align__(16) __nv_bfloat16 g_al[SEQ * EMB];
__device__ __align__(16) __nv_bfloat16 g_wqh[QKV3 * EMB];   // Wqkv^T split [N][K]
__device__ __align__(16) __nv_bfloat16 g_wql[QKV3 * EMB];
__device__ __align__(16) __nv_bfloat16 g_woh[EMB * EMB];    // Wout^T split [N][K]
__device__ __align__(16) __nv_bfloat16 g_wol[EMB * EMB];

__device__ __align__(16) __nv_bfloat16 g_kh[NH * SEQ * HD]; // K split, [h][tok][d]
__device__ __align__(16) __nv_bfloat16 g_kl[NH * SEQ * HD];
__device__ __align__(16) __nv_bfloat16 g_vh[NH * SEQ * HD]; // V split, [h][tok][d]
__device__ __align__(16) __nv_bfloat16 g_vl[NH * SEQ * HD];

// ---------------------------------------------------------------------------
// Split fp32 -> (hi, lo) bf16, elementwise (4 elems/thread)
// ---------------------------------------------------------------------------
__global__ void split_kernel(const float* __restrict__ src,
                             __nv_bfloat16* __restrict__ hi,
                             __nv_bfloat16* __restrict__ lo, int n4)
{
    const int i = blockIdx.x * blockDim.x + threadIdx.x;
    if (i >= n4) return;
    float4 v = ((const float4*)src)[i];
    __nv_bfloat16 h0 = __float2bfloat16(v.x), h1 = __float2bfloat16(v.y);
    __nv_bfloat16 h2 = __float2bfloat16(v.z), h3 = __float2bfloat16(v.w);
    __nv_bfloat162* hp = (__nv_bfloat162*)hi;
    __nv_bfloat162* lp = (__nv_bfloat162*)lo;
    hp[2 * i]     = __nv_bfloat162(h0, h1);
    hp[2 * i + 1] = __nv_bfloat162(h2, h3);
    lp[2 * i]     = __nv_bfloat162(__float2bfloat16(v.x - __bfloat162float(h0)),
                                   __float2bfloat16(v.y - __bfloat162float(h1)));
    lp[2 * i + 1] = __nv_bfloat162(__float2bfloat16(v.z - __bfloat162float(h2)),
                                   __float2bfloat16(v.w - __bfloat162float(h3)));
}

// ---------------------------------------------------------------------------
// Transpose + split: W[K][N] fp32 -> T{h,l}[N][K] bf16
// ---------------------------------------------------------------------------
__global__ void wtsplit_kernel(const float* __restrict__ W,
                               __nv_bfloat16* __restrict__ Th,
                               __nv_bfloat16* __restrict__ Tl, int K, int N)
{
    __shared__ float t[32][33];
    const int k0 = blockIdx.x * 32;
    const int n0 = blockIdx.y * 32;
    const int tx = threadIdx.x, ty = threadIdx.y;
    #pragma unroll
    for (int i = 0; i < 32; i += 8)
        t[ty + i][tx] = W[(size_t)(k0 + ty + i) * N + n0 + tx];
    __syncthreads();
    #pragma unroll
    for (int i = 0; i < 32; i += 8) {
        const float v = t[tx][ty + i];
        const __nv_bfloat16 h = __float2bfloat16(v);
        const size_t o = (size_t)(n0 + ty + i) * K + k0 + tx;
        Th[o] = h;
        Tl[o] = __float2bfloat16(v - __bfloat162float(h));
    }
}

// ---------------------------------------------------------------------------
// K/V prep: split K and V to bf16 hi/lo, per-head layout [h][tok][64].
// ---------------------------------------------------------------------------
__global__ void kvsplit_kernel(const float* __restrict__ qkv,
                               __nv_bfloat16* __restrict__ kh,
                               __nv_bfloat16* __restrict__ kl,
                               __nv_bfloat16* __restrict__ vh,
                               __nv_bfloat16* __restrict__ vl)
{
    const int t = blockIdx.x;
    const int i = threadIdx.x;               // 0..191
    const int h = (4 * i) >> 6, d = (4 * i) & 63;
    const size_t o = ((size_t)h * SEQ + t) * HD + d;

    float4 kv = *(const float4*)&qkv[(size_t)t * QKV3 + 768 + 4 * i];
    {
        __nv_bfloat16 h0 = __float2bfloat16(kv.x), h1 = __float2bfloat16(kv.y);
        __nv_bfloat16 h2 = __float2bfloat16(kv.z), h3 = __float2bfloat16(kv.w);
        *(__nv_bfloat162*)&kh[o]     = __nv_bfloat162(h0, h1);
        *(__nv_bfloat162*)&kh[o + 2] = __nv_bfloat162(h2, h3);
        *(__nv_bfloat162*)&kl[o] =
            __nv_bfloat162(__float2bfloat16(kv.x - __bfloat162float(h0)),
                           __float2bfloat16(kv.y - __bfloat162float(h1)));
        *(__nv_bfloat162*)&kl[o + 2] =
            __nv_bfloat162(__float2bfloat16(kv.z - __bfloat162float(h2)),
                           __float2bfloat16(kv.w - __bfloat162float(h3)));
    }

    float4 vv = *(const float4*)&qkv[(size_t)t * QKV3 + 1536 + 4 * i];
    {
        __nv_bfloat16 h0 = __float2bfloat16(vv.x), h1 = __float2bfloat16(vv.y);
        __nv_bfloat16 h2 = __float2bfloat16(vv.z), h3 = __float2bfloat16(vv.w);
        *(__nv_bfloat162*)&vh[o]     = __nv_bfloat162(h0, h1);
        *(__nv_bfloat162*)&vh[o + 2] = __nv_bfloat162(h2, h3);
        *(__nv_bfloat162*)&vl[o] =
            __nv_bfloat162(__float2bfloat16(vv.x - __bfloat162float(h0)),
                           __float2bfloat16(vv.y - __bfloat162float(h1)));
        *(__nv_bfloat162*)&vl[o + 2] =
            __nv_bfloat162(__float2bfloat16(vv.z - __bfloat162float(h2)),
                           __float2bfloat16(vv.w - __bfloat162float(h3)));
    }
}

// ---------------------------------------------------------------------------
// bf16-split tensor-core GEMM — now 2 CTAs/SM (160KB smem, 128 regs)
// ---------------------------------------------------------------------------
#define GT_TILE  10240u   // 128 * 40 * 2 bytes
#define GT_STAGE 40960u   // 4 tiles (Ah,Al,Bh,Bl)

__global__ __launch_bounds__(256, 2)
void gemm_mma_kernel(const __nv_bfloat16* __restrict__ Ah,
                     const __nv_bfloat16* __restrict__ Al,
                     const __nv_bfloat16* __restrict__ Bh,
                     const __nv_bfloat16* __restrict__ Bl,
                     const float* __restrict__ bias,
                     float* __restrict__ C,
                     int M, int N, int K)
{
    extern __shared__ char gsm[];
    const uint32_t smB = (uint32_t)__cvta_generic_to_shared(gsm);

    const int tid  = threadIdx.x;
    const int warp = tid >> 5, lane = tid & 31;
    const int wm   = warp >> 2;
    const int wn   = warp & 3;
    const int m0   = blockIdx.y * 128;
    const int n0   = blockIdx.x * 128;

    float acc[4][4][4];
    #pragma unroll
    for (int a = 0; a < 4; a++)
        #pragma unroll
        for (int b = 0; b < 4; b++)
            #pragma unroll
            for (int c = 0; c < 4; c++) acc[a][b][c] = 0.0f;

    auto copyChunk = [&](int k0c, int buf) {
        const uint32_t sb = smB + (uint32_t)buf * GT_STAGE;
        #pragma unroll
        for (int t = 0; t < 4; t++) {
            const __nv_bfloat16* gp = (t == 0) ? Ah : (t == 1) ? Al : (t == 2) ? Bh : Bl;
            const int base = (t < 2) ? m0 : n0;
            #pragma unroll
            for (int s = 0; s < 2; s++) {
                const int cid = tid + 256 * s;
                const int row = cid >> 2, kc = cid & 3;
                cp_async16(sb + t * GT_TILE + (uint32_t)(row * 40 + kc * 8) * 2,
                           gp + (size_t)(base + row) * K + k0c + kc * 8);
            }
        }
        cp_commit();
    };

    const int T = K >> 5;
    copyChunk(0, 0);

    for (int it = 0; it < T; it++) {
        cp_wait0();
        __syncthreads();
        if (it + 1 < T) copyChunk((it + 1) << 5, (it + 1) & 1);

        const uint32_t stg = smB + (uint32_t)(it & 1) * GT_STAGE;
        const int arow = wm * 64 + (lane & 15);
        const int brow = wn * 32 + (lane & 15);
        const int chi  = (lane >> 4) * 8;

        #pragma unroll
        for (int ks = 0; ks < 2; ks++) {
            const int col = ks * 16 + chi;
            uint32_t b_h[2][4], b_l[2][4];
            #pragma unroll
            for (int nt = 0; nt < 2; nt++) {
                const uint32_t bd = stg + 2 * GT_TILE +
                                    (uint32_t)((brow + nt * 16) * 40 + col) * 2;
                LDSM_X4(b_h[nt], bd);
                LDSM_X4(b_l[nt], bd + GT_TILE);
            }
            #pragma unroll
            for (int mt = 0; mt < 4; mt++) {
                uint32_t a_h[4], a_l[4];
                const uint32_t ad = stg + (uint32_t)((arow + mt * 16) * 40 + col) * 2;
                LDSM_X4(a_h, ad);
                LDSM_X4(a_l, ad + GT_TILE);
                #pragma unroll
                for (int j = 0; j < 4; j++) {
                    const int nt = j >> 1, hf = j & 1;
                    mma16816(acc[mt][j], a_h, b_h[nt][hf], b_h[nt][hf + 2]);
                    mma16816(acc[mt][j], a_h, b_l[nt][hf], b_l[nt][hf + 2]);
                    mma16816(acc[mt][j], a_l, b_h[nt][hf], b_h[nt][hf + 2]);
                }
            }
        }
    }

    #pragma unroll
    for (int mt = 0; mt < 4; mt++) {
        const int r0 = m0 + wm * 64 + mt * 16 + (lane >> 2);
        #pragma unroll
        for (int j = 0; j < 4; j++) {
            const int cn = n0 + wn * 32 + j * 8 + 2 * (lane & 3);
            const float bx = bias[cn], by = bias[cn + 1];
            *(float2*)&C[(size_t)r0 * N + cn] =
                make_float2(acc[mt][j][0] + bx, acc[mt][j][1] + by);
            *(float2*)&C[(size_t)(r0 + 8) * N + cn] =
                make_float2(acc[mt][j][2] + bx, acc[mt][j][3] + by);
        }
    }
}

// ---------------------------------------------------------------------------
// Tensor-core strided flash attention, 3 branches in one launch.
// Block = 128 q x 1 head x 1 branch, 256 threads (8 warps x 16q).
// Q staging overlaps the K ring (Q frags read into regs BEFORE first copyKV)
// -> smem 73.7KB -> 2 CTAs/SM.
// ---------------------------------------------------------------------------
#define AP 72                       // smem pitch (bf16 elems)
#define A_QL   18432u               // Ql staging offset (within K-ring region)
#define A_V    36864u               // V ring base; K ring base = 0
#define A_SMEM 73728u

__global__ __launch_bounds__(256, 2)
void attn_mma_kernel(const float* __restrict__ qkv,
                     const __nv_bfloat16* __restrict__ kh,
                     const __nv_bfloat16* __restrict__ kl,
                     const __nv_bfloat16* __restrict__ vh,
                     const __nv_bfloat16* __restrict__ vl,
                     float* __restrict__ attn_out)
{
    extern __shared__ char asm_[];
    const uint32_t smB = (uint32_t)__cvta_generic_to_shared(asm_);

    const int br = blockIdx.z;
    int L, dil;
    if (br == 0)      { L = 2048; dil = 1; }
    else if (br == 1) { L = 4096; dil = 2; }
    else              { L = 2048; dil = 4; }

    const int q0 = blockIdx.x * 128;
    if (q0 >= L) return;
    const int h    = blockIdx.y;
    const int tid  = threadIdx.x;
    const int warp = tid >> 5, lane = tid & 31;

    const size_t hoff = (size_t)h * SEQ * HD;

    auto copyKV = [&](int kt, int buf) {
        const int tok0 = kt * 64;
        const uint32_t kb   = smB + (uint32_t)buf * 18432u;
        const uint32_t vbuf = smB + A_V + (uint32_t)buf * 18432u;
        #pragma unroll
        for (int i = 0; i < 8; i++) {
            const int flat = tid + 256 * i;          // 0..2047
            const int sel  = flat >> 9;              // 0:Kh 1:Kl 2:Vh 3:Vl
            const int r    = (flat >> 3) & 63;
            const int c    = flat & 7;
            const size_t src = hoff + (size_t)(tok0 + r) * dil * HD + c * 8;
            const uint32_t doff = (uint32_t)(r * AP + c * 8) * 2;
            const __nv_bfloat16* gp = (sel == 0) ? kh : (sel == 1) ? kl
                                     : (sel == 2) ? vh : vl;
            const uint32_t db = (sel == 0) ? kb : (sel == 1) ? kb + 9216u
                               : (sel == 2) ? vbuf : vbuf + 9216u;
            cp_async16(db + doff, gp + src);
        }
        cp_commit();
    };

    const int nkt = L >> 6;

    // Prologue: stage Q (scaled + split) into smem region that will later
    // hold the K ring; read fragments into registers; then start K/V copies.
    {
        const int qr = tid >> 1, qc0 = (tid & 1) * 32;
        const float* qsrc = qkv + (size_t)(q0 + qr) * dil * QKV3 + h * 64 + qc0;
        __nv_bfloat16* Qh = (__nv_bfloat16*)asm_;
        __nv_bfloat16* Ql = Qh + 128 * AP;
        #pragma unroll
        for (int i = 0; i < 8; i++) {
            float4 v = *(const float4*)&qsrc[4 * i];
            v.x *= QSCALE; v.y *= QSCALE; v.z *= QSCALE; v.w *= QSCALE;
            __nv_bfloat16 h0 = __float2bfloat16(v.x), h1 = __float2bfloat16(v.y);
            __nv_bfloat16 h2 = __float2bfloat16(v.z), h3 = __float2bfloat16(v.w);
            const int o = qr * AP + qc0 + 4 * i;
            *(__nv_bfloat162*)&Qh[o]     = __nv_bfloat162(h0, h1);
            *(__nv_bfloat162*)&Qh[o + 2] = __nv_bfloat162(h2, h3);
            *(__nv_bfloat162*)&Ql[o] =
                __nv_bfloat162(__float2bfloat16(v.x - __bfloat162float(h0)),
                               __float2bfloat16(v.y - __bfloat162float(h1)));
            *(__nv_bfloat162*)&Ql[o + 2] =
                __nv_bfloat162(__float2bfloat16(v.z - __bfloat162float(h2)),
                               __float2bfloat16(v.w - __bfloat162float(h3)));
        }
    }
    __syncthreads();

    // Per-warp Q fragments (held in registers for the whole block)
    uint32_t qfh[4][4], qfl[4][4];
    {
        const int qrow = 16 * warp + (lane & 15);
        #pragma unroll
        for (int ks = 0; ks < 4; ks++) {
            const uint32_t ad = smB + (uint32_t)(qrow * AP + ks * 16 + (lane >> 4) * 8) * 2;
            LDSM_X4(qfh[ks], ad);
            LDSM_X4(qfl[ks], ad + A_QL);
        }
    }
    __syncthreads();   // all warps done reading Q before K ring overwrites it

    copyKV(0, 0);

    float o[8][4];
    #pragma unroll
    for (int j = 0; j < 8; j++)
        #pragma unroll
        for (int c = 0; c < 4; c++) o[j][c] = 0.0f;
    float mrA = -1e30f, mrB = -1e30f, lrA = 0.0f, lrB = 0.0f;

    for (int kt = 0; kt < nkt; kt++) {
        cp_wait0();
        __syncthreads();
        if (kt + 1 < nkt) copyKV(kt + 1, (kt + 1) & 1);

        const int buf = kt & 1;
        const uint32_t kbase = smB + (uint32_t)buf * 18432u;
        const uint32_t vbase = smB + A_V + (uint32_t)buf * 18432u;

        // ---- S = Q K^T (3 split terms), per-group K frag loads ----
        float s[8][4];
        #pragma unroll
        for (int j = 0; j < 8; j++)
            #pragma unroll
            for (int c = 0; c < 4; c++) s[j][c] = 0.0f;

        #pragma unroll
        for (int ks = 0; ks < 4; ks++) {
            #pragma unroll
            for (int g = 0; g < 4; g++) {
                uint32_t khf[4], klf[4];
                const uint32_t ad = kbase +
                    (uint32_t)((g * 16 + (lane & 15)) * AP + ks * 16 + (lane >> 4) * 8) * 2;
                LDSM_X4(khf, ad);
                LDSM_X4(klf, ad + 9216u);
                mma16816(s[2 * g],     qfh[ks], khf[0], khf[2]);
                mma16816(s[2 * g + 1], qfh[ks], khf[1], khf[3]);
                mma16816(s[2 * g],     qfh[ks], klf[0], klf[2]);
                mma16816(s[2 * g + 1], qfh[ks], klf[1], klf[3]);
                mma16816(s[2 * g],     qfl[ks], khf[0], khf[2]);
                mma16816(s[2 * g + 1], qfl[ks], khf[1], khf[3]);
            }
        }

        // ---- online softmax (rows rA = lane>>2, rB = rA+8; quad shfl) ----
        float mA = -1e30f, mB = -1e30f;
        #pragma unroll
        for (int j = 0; j < 8; j++) {
            mA = fmaxf(mA, fmaxf(s[j][0], s[j][1]));
            mB = fmaxf(mB, fmaxf(s[j][2], s[j][3]));
        }
        mA = fmaxf(mA, __shfl_xor_sync(0xffffffffu, mA, 1));
        mA = fmaxf(mA, __shfl_xor_sync(0xffffffffu, mA, 2));
        mB = fmaxf(mB, __shfl_xor_sync(0xffffffffu, mB, 1));
        mB = fmaxf(mB, __shfl_xor_sync(0xffffffffu, mB, 2));

        const float mnA = fmaxf(mrA, mA), mnB = fmaxf(mrB, mB);
        const float alA = __expf(mrA - mnA), alB = __expf(mrB - mnB);
        mrA = mnA; mrB = mnB;

        float lsA = 0.0f, lsB = 0.0f;
        #pragma unroll
        for (int j = 0; j < 8; j++) {
            s[j][0] = __expf(s[j][0] - mnA);
            s[j][1] = __expf(s[j][1] - mnA);
            s[j][2] = __expf(s[j][2] - mnB);
            s[j][3] = __expf(s[j][3] - mnB);
            lsA += s[j][0] + s[j][1];
            lsB += s[j][2] + s[j][3];
        }
        lsA += __shfl_xor_sync(0xffffffffu, lsA, 1);
        lsA += __shfl_xor_sync(0xffffffffu, lsA, 2);
        lsB += __shfl_xor_sync(0xffffffffu, lsB, 1);
        lsB += __shfl_xor_sync(0xffffffffu, lsB, 2);
        lrA = lrA * alA + lsA;
        lrB = lrB * alB + lsB;

        // rescale O
        #pragma unroll
        for (int j = 0; j < 8; j++) {
            o[j][0] *= alA; o[j][1] *= alA;
            o[j][2] *= alB; o[j][3] *= alB;
        }

        // ---- O += P V  (P split in registers; V split in smem; 3 terms) ----
        #pragma unroll
        for (int t = 0; t < 4; t++) {
            uint32_t pah[4], pal[4];
            psplit(s[2 * t][0],     s[2 * t][1],     pah[0], pal[0]);
            psplit(s[2 * t][2],     s[2 * t][3],     pah[1], pal[1]);
            psplit(s[2 * t + 1][0], s[2 * t + 1][1], pah[2], pal[2]);
            psplit(s[2 * t + 1][2], s[2 * t + 1][3], pah[3], pal[3]);
            #pragma unroll
            for (int g = 0; g < 4; g++) {
                uint32_t vfh[4], vfl[4];
                const uint32_t ad = vbase +
                    (uint32_t)((16 * t + ((lane >> 3) & 1) * 8 + (lane & 7)) * AP +
                               16 * g + (lane >> 4) * 8) * 2;
                LDSM_X4_T(vfh, ad);
                LDSM_X4_T(vfl, ad + 9216u);
                mma16816(o[2 * g],     pah, vfh[0], vfh[1]);
                mma16816(o[2 * g + 1], pah, vfh[2], vfh[3]);
                mma16816(o[2 * g],     pah, vfl[0], vfl[1]);
                mma16816(o[2 * g + 1], pah, vfl[2], vfl[3]);
                mma16816(o[2 * g],     pal, vfh[0], vfh[1]);
                mma16816(o[2 * g + 1], pal, vfh[2], vfh[3]);
            }
        }
    }

    // Epilogue: o/l * (1/3), scatter-add
    const float w3 = 1.0f / 3.0f;
    const float invA = w3 / lrA, invB = w3 / lrB;
    const int rA = q0 + 16 * warp + (lane >> 2);
    float* baseA = attn_out + (size_t)rA * dil * EMB + h * 64;
    float* baseB = attn_out + (size_t)(rA + 8) * dil * EMB + h * 64;
    #pragma unroll
    for (int j = 0; j < 8; j++) {
        const int c = 8 * j + 2 * (lane & 3);
        atomicAdd(baseA + c,     o[j][0] * invA);
        atomicAdd(baseA + c + 1, o[j][1] * invA);
        atomicAdd(baseB + c,     o[j][2] * invB);
        atomicAdd(baseB + c + 1, o[j][3] * invB);
    }
}

// ---------------------------------------------------------------------------
// Launch
// ---------------------------------------------------------------------------
extern "C" void kernel_launch(void* const* d_in, const int* in_sizes, int n_in,
                              void* d_out, int out_size)
{
    const float* x    = (const float*)d_in[0];
    const float* Wqkv = (const float*)d_in[1];
    const float* bqkv = (const float*)d_in[2];
    const float* Wout = (const float*)d_in[3];
    const float* bout = (const float*)d_in[4];
    float*       out  = (float*)d_out;

    float *qkvp, *attnp;
    __nv_bfloat16 *xh, *xl, *ah, *al, *wqh, *wql, *woh, *wol, *khp, *klp, *vhp, *vlp;
    cudaGetSymbolAddress((void**)&qkvp,  g_qkv);
    cudaGetSymbolAddress((void**)&attnp, g_attn);
    cudaGetSymbolAddress((void**)&xh,  g_xh);  cudaGetSymbolAddress((void**)&xl,  g_xl);
    cudaGetSymbolAddress((void**)&ah,  g_ah);  cudaGetSymbolAddress((void**)&al,  g_al);
    cudaGetSymbolAddress((void**)&wqh, g_wqh); cudaGetSymbolAddress((void**)&wql, g_wql);
    cudaGetSymbolAddress((void**)&woh, g_woh); cudaGetSymbolAddress((void**)&wol, g_wol);
    cudaGetSymbolAddress((void**)&khp, g_kh);  cudaGetSymbolAddress((void**)&klp, g_kl);
    cudaGetSymbolAddress((void**)&vhp, g_vh);  cudaGetSymbolAddress((void**)&vlp, g_vl);

    const int GEMM_SMEM = 2 * GT_STAGE;   // 81920
    (void)cudaFuncSetAttribute((const void*)gemm_mma_kernel,
                               cudaFuncAttributeMaxDynamicSharedMemorySize, GEMM_SMEM);
    (void)cudaFuncSetAttribute((const void*)attn_mma_kernel,
                               cudaFuncAttributeMaxDynamicSharedMemorySize, A_SMEM);

    // 1) Split inputs to bf16 hi/lo
    split_kernel<<<(SEQ * EMB / 4 + 255) / 256, 256>>>(x, xh, xl, SEQ * EMB / 4);
    wtsplit_kernel<<<dim3(EMB / 32, QKV3 / 32), dim3(32, 8)>>>(Wqkv, wqh, wql, EMB, QKV3);
    wtsplit_kernel<<<dim3(EMB / 32, EMB / 32),  dim3(32, 8)>>>(Wout, woh, wol, EMB, EMB);

    // 2) QKV GEMM (tensor cores, bf16 split)
    {
        dim3 grid(QKV3 / 128, SEQ / 128);
        gemm_mma_kernel<<<grid, 256, GEMM_SMEM>>>(xh, xl, wqh, wql, bqkv, qkvp,
                                                  SEQ, QKV3, EMB);
    }

    // 3) K/V split to per-head bf16 hi/lo
    kvsplit_kernel<<<SEQ, 192>>>(qkvp, khp, klp, vhp, vlp);

    // 4) Zero attention accumulator
    cudaMemsetAsync(attnp, 0, (size_t)SEQ * EMB * sizeof(float));

    // 5) Attention (tensor cores, all 3 branches)
    {
        dim3 grid(32, NH, 3);
        attn_mma_kernel<<<grid, 256, A_SMEM>>>(qkvp, khp, klp, vhp, vlp, attnp);
    }

    // 6) Split attention output, then output projection (tensor cores)
    split_kernel<<<(SEQ * EMB / 4 + 255) / 256, 256>>>(attnp, ah, al, SEQ * EMB / 4);
    {
        dim3 grid(EMB / 128, SEQ / 128);
        gemm_mma_kernel<<<grid, 256, GEMM_SMEM>>>(ah, al, woh, wol, bout, out,
                                                  SEQ, EMB, EMB);
    }
}